// round 4
// baseline (speedup 1.0000x reference)
#include <cuda_runtime.h>
#include <math.h>

#define B_ 4
#define M_ 2048
#define E_ 1024
#define D_ 256
#define H_ 8
#define DH_ 32
#define SPLITK 4
#define KCH (M_ / SPLITK)   // 512
#define ESPL 32
#define ECH (E_ / ESPL)     // 32

// ---------------- scratch (device globals: allocation-free) ----------------
__device__ float g_q[B_*H_*M_*DH_];
__device__ float g_k[B_*H_*M_*DH_];
__device__ float g_v[B_*H_*M_*DH_];
__device__ float g_attn[B_*M_*D_];
__device__ float g_attnout[B_*M_*D_];
__device__ float g_Spart[SPLITK*B_*E_*D_];
__device__ float g_S[B_*E_*D_];
__device__ float g_ef[B_*E_*D_];
__device__ float g_ef2[B_*E_*D_];
__device__ float g_m1[B_*ESPL*D_];
__device__ float g_l1[B_*ESPL*D_];
__device__ float g_mg[B_*D_];
__device__ float g_li[B_*D_];

// ---------------- helpers ---------------------------------------------------
// D += A@B, m16n8k8 tf32 (operands are raw fp32 bit patterns; HW truncates)
__device__ __forceinline__ void mma8(float* d, const unsigned* a, const unsigned* b) {
    asm volatile(
        "mma.sync.aligned.m16n8k8.row.col.f32.tf32.tf32.f32 "
        "{%0,%1,%2,%3},{%4,%5,%6,%7},{%8,%9},{%0,%1,%2,%3};"
        : "+f"(d[0]), "+f"(d[1]), "+f"(d[2]), "+f"(d[3])
        : "r"(a[0]), "r"(a[1]), "r"(a[2]), "r"(a[3]), "r"(b[0]), "r"(b[1]));
}
__device__ __forceinline__ void cp16(void* dst, const void* src) {
    unsigned s = (unsigned)__cvta_generic_to_shared(dst);
    asm volatile("cp.async.cg.shared.global [%0], [%1], 16;" :: "r"(s), "l"(src));
}
#define CP_COMMIT asm volatile("cp.async.commit_group;")
#define CP_WAIT1  asm volatile("cp.async.wait_group 1;" ::: "memory")

// ---------------- NT tf32 GEMM: C[M,N] = A[M,K] @ Bw[N,K]^T (+bias) --------
// 128x128x32 tile, 256 thr, warp tile 64x32. Double-buffered cp.async.
// EPI==0: plain store. EPI==1: scatter into g_q/g_k/g_v [bh,m,dh].
#define NT_STG (128*36)
template<int EPI>
__global__ __launch_bounds__(256, 2)
void gemm_nt_tf32(const float* __restrict__ A, const float* __restrict__ Bw,
                  const float* __restrict__ bias, float* __restrict__ C,
                  int M, int N, int K)
{
    extern __shared__ unsigned sm[];
    unsigned* As = sm;              // [2][128][36]
    unsigned* Bs = sm + 2*NT_STG;   // [2][128][36]
    const int t = threadIdx.x, lane = t & 31, w = t >> 5;
    const int m0 = blockIdx.y * 128, n0 = blockIdx.x * 128;
    const int wm = (w & 1) * 64, wn = (w >> 1) * 32;
    const int g = lane >> 2, qt = lane & 3;

    auto issue = [&](int st, int k0) {
#pragma unroll
        for (int p = 0; p < 4; p++) {
            int lin = p * 1024 + t * 4;
            int r = lin >> 5, c = lin & 31;
            cp16(&As[st*NT_STG + r*36 + c], A  + (size_t)(m0 + r) * K + k0 + c);
            cp16(&Bs[st*NT_STG + r*36 + c], Bw + (size_t)(n0 + r) * K + k0 + c);
        }
    };

    float acc[4][4][4];
#pragma unroll
    for (int i = 0; i < 4; i++)
#pragma unroll
        for (int j = 0; j < 4; j++)
#pragma unroll
            for (int r = 0; r < 4; r++) acc[i][j][r] = 0.f;

    issue(0, 0); CP_COMMIT;
    const int NIT = K >> 5;
    for (int it = 0; it < NIT; it++) {
        const int st = it & 1;
        if (it + 1 < NIT) issue(st ^ 1, (it + 1) * 32);
        CP_COMMIT; CP_WAIT1;
        __syncthreads();
        const unsigned* Asb = As + st*NT_STG;
        const unsigned* Bsb = Bs + st*NT_STG;
#pragma unroll
        for (int ks = 0; ks < 4; ks++) {
            unsigned af[4][4], bf[4][2];
            const int kc = ks * 8 + qt;
#pragma unroll
            for (int mt = 0; mt < 4; mt++) {
                const int mr = wm + mt * 16 + g;
                af[mt][0] = Asb[mr*36 + kc];     af[mt][1] = Asb[(mr+8)*36 + kc];
                af[mt][2] = Asb[mr*36 + kc+4];   af[mt][3] = Asb[(mr+8)*36 + kc+4];
            }
#pragma unroll
            for (int nt = 0; nt < 4; nt++) {
                const int nr = wn + nt * 8 + g;
                bf[nt][0] = Bsb[nr*36 + kc];     bf[nt][1] = Bsb[nr*36 + kc+4];
            }
#pragma unroll
            for (int mt = 0; mt < 4; mt++)
#pragma unroll
                for (int nt = 0; nt < 4; nt++)
                    mma8(acc[mt][nt], af[mt], bf[nt]);
        }
        __syncthreads();
    }

#pragma unroll
    for (int mt = 0; mt < 4; mt++) {
#pragma unroll
        for (int nt = 0; nt < 4; nt++) {
            const int n = n0 + wn + nt * 8 + 2 * qt;
            float b0 = bias ? bias[n] : 0.f;
            float b1 = bias ? bias[n+1] : 0.f;
#pragma unroll
            for (int rh = 0; rh < 2; rh++) {
                const int m = m0 + wm + mt * 16 + g + rh * 8;
                float v0 = acc[mt][nt][rh*2] + b0;
                float v1 = acc[mt][nt][rh*2+1] + b1;
                if (EPI == 0) {
                    *(float2*)(C + (size_t)m * N + n) = make_float2(v0, v1);
                } else {
                    int bi = m >> 11, mm = m & (M_ - 1);
                    int which = n >> 8, dd = n & 255;
                    int h = dd >> 5, c = dd & 31;
                    float* dst = (which == 0 ? g_q : which == 1 ? g_k : g_v)
                               + (size_t)(((bi << 3) + h) * M_ + mm) * DH_ + c;
                    *(float2*)dst = make_float2(v0, v1);
                }
            }
        }
    }
}

// ---------------- TN tf32 GEMM (split-K): S_partial = inc^T @ attnout ------
#define TN_STG (32*132)
__global__ __launch_bounds__(256, 2)
void gemm_tn_S_tf32(const float* __restrict__ inc)
{
    extern __shared__ unsigned sm[];
    unsigned* As = sm;              // [2][32][132]  [token][e]
    unsigned* Bs = sm + 2*TN_STG;   // [2][32][132]  [token][d]
    const int t = threadIdx.x, lane = t & 31, w = t >> 5;
    const int z = blockIdx.z;
    const int b = z >> 2, sk = z & 3;
    const int e0 = blockIdx.y * 128, d0 = blockIdx.x * 128;
    const int kbase = sk * KCH;
    const int wm = (w & 1) * 64, wn = (w >> 1) * 32;
    const int g = lane >> 2, qt = lane & 3;
    const float* Ag = inc       + (size_t)b * M_ * E_;
    const float* Bg = g_attnout + (size_t)b * M_ * D_;

    auto issue = [&](int st, int k0) {
#pragma unroll
        for (int p = 0; p < 4; p++) {
            int lin = p * 1024 + t * 4;
            int r = lin >> 7, c = lin & 127;
            int krow = kbase + k0 + r;
            cp16(&As[st*TN_STG + r*132 + c], Ag + (size_t)krow * E_ + e0 + c);
            cp16(&Bs[st*TN_STG + r*132 + c], Bg + (size_t)krow * D_ + d0 + c);
        }
    };

    float acc[4][4][4];
#pragma unroll
    for (int i = 0; i < 4; i++)
#pragma unroll
        for (int j = 0; j < 4; j++)
#pragma unroll
            for (int r = 0; r < 4; r++) acc[i][j][r] = 0.f;

    issue(0, 0); CP_COMMIT;
    const int NIT = KCH >> 5;
    for (int it = 0; it < NIT; it++) {
        const int st = it & 1;
        if (it + 1 < NIT) issue(st ^ 1, (it + 1) * 32);
        CP_COMMIT; CP_WAIT1;
        __syncthreads();
        const unsigned* Asb = As + st*TN_STG;
        const unsigned* Bsb = Bs + st*TN_STG;
#pragma unroll
        for (int ks = 0; ks < 4; ks++) {
            unsigned af[4][4], bf[4][2];
            const int kc = ks * 8 + qt;
#pragma unroll
            for (int mt = 0; mt < 4; mt++) {
                const int mr = wm + mt * 16 + g;
                af[mt][0] = Asb[kc*132 + mr];     af[mt][1] = Asb[kc*132 + mr+8];
                af[mt][2] = Asb[(kc+4)*132 + mr]; af[mt][3] = Asb[(kc+4)*132 + mr+8];
            }
#pragma unroll
            for (int nt = 0; nt < 4; nt++) {
                const int nr = wn + nt * 8 + g;
                bf[nt][0] = Bsb[kc*132 + nr];     bf[nt][1] = Bsb[(kc+4)*132 + nr];
            }
#pragma unroll
            for (int mt = 0; mt < 4; mt++)
#pragma unroll
                for (int nt = 0; nt < 4; nt++)
                    mma8(acc[mt][nt], af[mt], bf[nt]);
        }
        __syncthreads();
    }

    float* Cp = g_Spart + (size_t)(sk * B_ + b) * E_ * D_;
#pragma unroll
    for (int mt = 0; mt < 4; mt++)
#pragma unroll
        for (int nt = 0; nt < 4; nt++) {
            const int d = d0 + wn + nt * 8 + 2 * qt;
#pragma unroll
            for (int rh = 0; rh < 2; rh++) {
                const int e = e0 + wm + mt * 16 + g + rh * 8;
                *(float2*)(Cp + (size_t)e * D_ + d) =
                    make_float2(acc[mt][nt][rh*2], acc[mt][nt][rh*2+1]);
            }
        }
}

// ---------------- tensor-core flash attention ------------------------------
// 256 thr (8 warps), warp owns 32 q. K/V double-buffered cp.async.
// P never hits smem: acc fragments permuted to A-layout via quad shuffles.
#define FTK 64
#define KVS 36
__global__ __launch_bounds__(256, 2)
void flash_attn_tf32()
{
    __shared__ unsigned Ks[2][FTK*KVS];
    __shared__ unsigned Vs[2][FTK*KVS];
    const int t = threadIdx.x, lane = t & 31, w = t >> 5;
    const int g = lane >> 2, qt = lane & 3;
    const int bh = blockIdx.y;
    const int qbase = blockIdx.x * 256 + w * 32;

    const float scale = 0.17677669529663687f;   // 1/sqrt(32)
    const float* qp = g_q + ((size_t)bh * M_ + qbase) * DH_;
    unsigned qf[2][4][4];
#pragma unroll
    for (int mt = 0; mt < 2; mt++)
#pragma unroll
        for (int ks = 0; ks < 4; ks++) {
            int r0 = mt * 16 + g, c0 = ks * 8 + qt;
            qf[mt][ks][0] = __float_as_uint(scale * qp[r0*32 + c0]);
            qf[mt][ks][1] = __float_as_uint(scale * qp[(r0+8)*32 + c0]);
            qf[mt][ks][2] = __float_as_uint(scale * qp[r0*32 + c0 + 4]);
            qf[mt][ks][3] = __float_as_uint(scale * qp[(r0+8)*32 + c0 + 4]);
        }

    float of[2][4][4];
#pragma unroll
    for (int i = 0; i < 2; i++)
#pragma unroll
        for (int j = 0; j < 4; j++)
#pragma unroll
            for (int r = 0; r < 4; r++) of[i][j][r] = 0.f;
    float mr[2][2] = {{-1e30f,-1e30f},{-1e30f,-1e30f}};
    float lr[2][2] = {{0.f,0.f},{0.f,0.f}};

    const float* kb = g_k + (size_t)bh * M_ * DH_;
    const float* vb = g_v + (size_t)bh * M_ * DH_;

    auto issue = [&](int st, int kt) {
#pragma unroll
        for (int p = 0; p < 2; p++) {
            int lin = p * 1024 + t * 4;
            int r = lin >> 5, c = lin & 31;
            cp16(&Ks[st][r*KVS + c], kb + (size_t)(kt + r) * DH_ + c);
            cp16(&Vs[st][r*KVS + c], vb + (size_t)(kt + r) * DH_ + c);
        }
    };

    const int srcA = (lane & ~3) | (qt >> 1);
    const int srcB = srcA | 2;
    const bool odd = qt & 1;

    issue(0, 0); CP_COMMIT;
    for (int it = 0; it < M_/FTK; it++) {
        const int st = it & 1;
        if (it + 1 < M_/FTK) issue(st ^ 1, (it + 1) * FTK);
        CP_COMMIT; CP_WAIT1;
        __syncthreads();

#pragma unroll
        for (int half = 0; half < 2; half++) {
            const unsigned* Kst = &Ks[st][half * 32 * KVS];
            const unsigned* Vst = &Vs[st][0];

            // S = Q @ K^T  (32q x 32keys)
            float sf[2][4][4];
#pragma unroll
            for (int i = 0; i < 2; i++)
#pragma unroll
                for (int j = 0; j < 4; j++)
#pragma unroll
                    for (int r = 0; r < 4; r++) sf[i][j][r] = 0.f;
#pragma unroll
            for (int ks = 0; ks < 4; ks++) {
                unsigned bfk[4][2];
                const int kc = ks * 8 + qt;
#pragma unroll
                for (int n = 0; n < 4; n++) {
                    bfk[n][0] = Kst[(n*8 + g)*KVS + kc];
                    bfk[n][1] = Kst[(n*8 + g)*KVS + kc + 4];
                }
#pragma unroll
                for (int mt = 0; mt < 2; mt++)
#pragma unroll
                    for (int n = 0; n < 4; n++)
                        mma8(sf[mt][n], qf[mt][ks], bfk[n]);
            }

            // online softmax on fragments, overwrite sf with exp values
#pragma unroll
            for (int mt = 0; mt < 2; mt++) {
#pragma unroll
                for (int rh = 0; rh < 2; rh++) {
                    float mx = -1e30f;
#pragma unroll
                    for (int n = 0; n < 4; n++) {
                        mx = fmaxf(mx, sf[mt][n][rh*2]);
                        mx = fmaxf(mx, sf[mt][n][rh*2+1]);
                    }
                    mx = fmaxf(mx, __shfl_xor_sync(~0u, mx, 1));
                    mx = fmaxf(mx, __shfl_xor_sync(~0u, mx, 2));
                    float mn = fmaxf(mr[mt][rh], mx);
                    float corr = __expf(mr[mt][rh] - mn);
                    mr[mt][rh] = mn;
                    lr[mt][rh] *= corr;
#pragma unroll
                    for (int nd = 0; nd < 4; nd++) {
                        of[mt][nd][rh*2]   *= corr;
                        of[mt][nd][rh*2+1] *= corr;
                    }
                    float ls = 0.f;
#pragma unroll
                    for (int n = 0; n < 4; n++) {
                        float e0 = __expf(sf[mt][n][rh*2]   - mn);
                        float e1 = __expf(sf[mt][n][rh*2+1] - mn);
                        ls += e0 + e1;
                        sf[mt][n][rh*2] = e0; sf[mt][n][rh*2+1] = e1;
                    }
                    lr[mt][rh] += ls;
                }
            }

            // O += P @ V : permute acc->A layout via quad shuffles
#pragma unroll
            for (int ks = 0; ks < 4; ks++) {
                unsigned bfv[4][2];
                const int kc = half * 32 + ks * 8 + qt;
#pragma unroll
                for (int nd = 0; nd < 4; nd++) {
                    bfv[nd][0] = Vst[kc*KVS + nd*8 + g];
                    bfv[nd][1] = Vst[(kc+4)*KVS + nd*8 + g];
                }
#pragma unroll
                for (int mt = 0; mt < 2; mt++) {
                    float aA0 = __shfl_sync(~0u, sf[mt][ks][0], srcA);
                    float aA1 = __shfl_sync(~0u, sf[mt][ks][1], srcA);
                    float aA2 = __shfl_sync(~0u, sf[mt][ks][2], srcA);
                    float aA3 = __shfl_sync(~0u, sf[mt][ks][3], srcA);
                    float aB0 = __shfl_sync(~0u, sf[mt][ks][0], srcB);
                    float aB1 = __shfl_sync(~0u, sf[mt][ks][1], srcB);
                    float aB2 = __shfl_sync(~0u, sf[mt][ks][2], srcB);
                    float aB3 = __shfl_sync(~0u, sf[mt][ks][3], srcB);
                    unsigned af[4];
                    af[0] = __float_as_uint(odd ? aA1 : aA0);   // [g][qt]
                    af[1] = __float_as_uint(odd ? aA3 : aA2);   // [g+8][qt]
                    af[2] = __float_as_uint(odd ? aB1 : aB0);   // [g][qt+4]
                    af[3] = __float_as_uint(odd ? aB3 : aB2);   // [g+8][qt+4]
#pragma unroll
                    for (int nd = 0; nd < 4; nd++)
                        mma8(of[mt][nd], af, bfv[nd]);
                }
            }
        }
        __syncthreads();
    }

    // finalize + store into g_attn [b][m][h*32 + d]
    const int b = bh >> 3, h = bh & 7;
#pragma unroll
    for (int mt = 0; mt < 2; mt++)
#pragma unroll
        for (int rh = 0; rh < 2; rh++) {
            float l = lr[mt][rh];
            l += __shfl_xor_sync(~0u, l, 1);
            l += __shfl_xor_sync(~0u, l, 2);
            float inv = 1.f / l;
            const int q = qbase + mt*16 + g + rh*8;
            float* op = g_attn + ((size_t)b * M_ + q) * D_ + h * DH_;
#pragma unroll
            for (int nd = 0; nd < 4; nd++)
                *(float2*)(op + nd*8 + 2*qt) =
                    make_float2(of[mt][nd][rh*2]*inv, of[mt][nd][rh*2+1]*inv);
        }
}

// ---------------- fused split-K reduce + column softmax --------------------
// pass1: reduce 4 partials -> g_S, online (max,sum) per (b,d) over e-chunk
__global__ void sm_pass1()
{
    const int b = blockIdx.y, ec = blockIdx.x, d = threadIdx.x;
    const size_t NB = (size_t)B_*E_*D_;
    size_t off = ((size_t)b*E_ + ec*ECH)*D_ + d;
    float m = -1e30f, l = 0.f;
    for (int e = 0; e < ECH; e++) {
        size_t idx = off + (size_t)e*D_;
        float s = g_Spart[idx] + g_Spart[idx+NB] + g_Spart[idx+2*NB] + g_Spart[idx+3*NB];
        g_S[idx] = s;
        float mn = fmaxf(m, s);
        l = l*__expf(m - mn) + __expf(s - mn);
        m = mn;
    }
    g_m1[(b*ESPL + ec)*D_ + d] = m;
    g_l1[(b*ESPL + ec)*D_ + d] = l;
}
__global__ void sm_combine()
{
    const int b = blockIdx.x, d = threadIdx.x;
    float M = -1e30f, L = 0.f;
    for (int ec = 0; ec < ESPL; ec++) {
        float m = g_m1[(b*ESPL + ec)*D_ + d];
        float l = g_l1[(b*ESPL + ec)*D_ + d];
        float Mn = fmaxf(M, m);
        L = L*__expf(M - Mn) + l*__expf(m - Mn);
        M = Mn;
    }
    g_mg[b*D_ + d] = M;
    g_li[b*D_ + d] = 1.f / L;
}
__global__ void sm_pass2()
{
    const int b = blockIdx.y, ec = blockIdx.x, d = threadIdx.x;
    const float M = g_mg[b*D_ + d], Li = g_li[b*D_ + d];
    size_t off = ((size_t)b*E_ + ec*ECH)*D_ + d;
    for (int e = 0; e < ECH; e++) {
        size_t idx = off + (size_t)e*D_;
        float s = g_S[idx];
        g_ef[idx] = s * __expf(s - M) * Li;
    }
}

// ---------------- LayerNorm + residual -------------------------------------
__global__ void ln_residual(const float* __restrict__ prev,
                            const float* __restrict__ gamma,
                            const float* __restrict__ beta,
                            const float* __restrict__ alphap,
                            float* __restrict__ out)
{
    const int t = threadIdx.x, lane = t & 31, wid = t >> 5;
    const int row = blockIdx.x * 8 + wid;
    const float* x = g_ef2 + (size_t)row * D_;
    float xs[8], sum = 0.f, sq = 0.f;
#pragma unroll
    for (int c = 0; c < 8; c++) {
        float v = x[lane + c*32];
        xs[c] = v; sum += v; sq += v*v;
    }
#pragma unroll
    for (int off = 16; off; off >>= 1) {
        sum += __shfl_xor_sync(~0u, sum, off);
        sq  += __shfl_xor_sync(~0u, sq,  off);
    }
    const float mu   = sum * (1.f / D_);
    const float var  = sq * (1.f / D_) - mu * mu;
    const float rstd = rsqrtf(var + 1e-5f);
    const float alpha = *alphap;
#pragma unroll
    for (int c = 0; c < 8; c++) {
        int d = lane + c*32;
        float y = (xs[c] - mu) * rstd * gamma[d] + beta[d];
        size_t idx = (size_t)row * D_ + d;
        out[idx] = (1.f + alpha) * prev[idx] + (1.f - alpha) * y;
    }
}

// ---------------- launch ----------------------------------------------------
extern "C" void kernel_launch(void* const* d_in, const int* in_sizes, int n_in,
                              void* d_out, int out_size)
{
    const float* feature = (const float*)d_in[0];
    const float* inc     = (const float*)d_in[1];
    const float* prev    = (const float*)d_in[2];
    const float* inw     = (const float*)d_in[3];
    const float* inb     = (const float*)d_in[4];
    const float* outw    = (const float*)d_in[5];
    const float* outb    = (const float*)d_in[6];
    const float* projw   = (const float*)d_in[7];
    const float* gamma   = (const float*)d_in[8];
    const float* beta    = (const float*)d_in[9];
    const float* alphap  = (const float*)d_in[10];
    float* out = (float*)d_out;

    float *p_attn = 0, *p_attnout = 0, *p_ef = 0, *p_ef2 = 0;
    cudaGetSymbolAddress((void**)&p_attn,    g_attn);
    cudaGetSymbolAddress((void**)&p_attnout, g_attnout);
    cudaGetSymbolAddress((void**)&p_ef,      g_ef);
    cudaGetSymbolAddress((void**)&p_ef2,     g_ef2);

    const int NT_SMEM = 2 * NT_STG * 2 * 4;   // 73728
    const int TN_SMEM = 2 * TN_STG * 2 * 4;   // 67584
    cudaFuncSetAttribute(gemm_nt_tf32<0>,
                         cudaFuncAttributeMaxDynamicSharedMemorySize, NT_SMEM);
    cudaFuncSetAttribute(gemm_nt_tf32<1>,
                         cudaFuncAttributeMaxDynamicSharedMemorySize, NT_SMEM);
    cudaFuncSetAttribute(gemm_tn_S_tf32,
                         cudaFuncAttributeMaxDynamicSharedMemorySize, TN_SMEM);

    // 1. QKV projection -> scatter to q/k/v
    gemm_nt_tf32<1><<<dim3(6, 64), 256, NT_SMEM>>>(feature, inw, inb, (float*)0,
                                                   B_*M_, 3*D_, D_);
    // 2. attention
    flash_attn_tf32<<<dim3(8, 32), 256>>>();
    // 3. out_proj
    gemm_nt_tf32<0><<<dim3(2, 64), 256, NT_SMEM>>>(p_attn, outw, outb, p_attnout,
                                                   B_*M_, D_, D_);
    // 4. S = inc^T @ attnout (split-K partials)
    gemm_tn_S_tf32<<<dim3(2, 8, B_*SPLITK), 256, TN_SMEM>>>(inc);
    // 5. fused reduce + softmax over e + ef = S*W
    sm_pass1<<<dim3(ESPL, B_), 256>>>();
    sm_combine<<<B_, 256>>>();
    sm_pass2<<<dim3(ESPL, B_), 256>>>();
    // 6. final projection
    gemm_nt_tf32<0><<<dim3(2, 32), 256, NT_SMEM>>>(p_ef, projw, (float*)0, p_ef2,
                                                   B_*E_, D_, D_);
    // 7. LN + residual mix
    ln_residual<<<512, 256>>>(prev, gamma, beta, alphap, out);
}

// round 7
// speedup vs baseline: 1.2646x; 1.2646x over previous
#include <cuda_runtime.h>
#include <math.h>

#define B_ 4
#define M_ 2048
#define E_ 1024
#define D_ 256
#define H_ 8
#define DH_ 32
#define SPLITK 4
#define KCH (M_ / SPLITK)   // 512
#define ESPL 32
#define ECH (E_ / ESPL)     // 32

// ---------------- scratch (device globals: allocation-free) ----------------
__device__ float g_q[B_*H_*M_*DH_];
__device__ float g_k[B_*H_*M_*DH_];
__device__ float g_v[B_*H_*M_*DH_];
__device__ float g_attn[B_*M_*D_];
__device__ float g_attnout[B_*M_*D_];
__device__ float g_Spart[SPLITK*B_*E_*D_];
__device__ float g_S[B_*E_*D_];
__device__ float g_ef[B_*E_*D_];
__device__ float g_ef2[B_*E_*D_];
__device__ float g_m1[B_*ESPL*D_];
__device__ float g_l1[B_*ESPL*D_];
__device__ float g_mg[B_*D_];
__device__ float g_li[B_*D_];

// ---------------- tf32 helpers ---------------------------------------------
__device__ __forceinline__ unsigned f2tf(float f) {
    unsigned u;
    asm("cvt.rna.tf32.f32 %0, %1;" : "=r"(u) : "f"(f));
    return u;
}
// D += A@B, m16n8k8 tf32
__device__ __forceinline__ void mma8(float* d, const unsigned* a, const unsigned* b) {
    asm volatile(
        "mma.sync.aligned.m16n8k8.row.col.f32.tf32.tf32.f32 "
        "{%0,%1,%2,%3},{%4,%5,%6,%7},{%8,%9},{%0,%1,%2,%3};"
        : "+f"(d[0]), "+f"(d[1]), "+f"(d[2]), "+f"(d[3])
        : "r"(a[0]), "r"(a[1]), "r"(a[2]), "r"(a[3]), "r"(b[0]), "r"(b[1]));
}

// ---------------- NT tf32 GEMM: C[M,N] = A[M,K] @ Bw[N,K]^T (+bias) --------
// 128x128x32 tile, 256 thr (8 warps 2x4), warp tile 64x32
// EPI==0: plain store. EPI==1: scatter into g_q/g_k/g_v [bh,m,dh].
template<int EPI>
__global__ __launch_bounds__(256, 2)
void gemm_nt_tf32(const float* __restrict__ A, const float* __restrict__ Bw,
                  const float* __restrict__ bias, float* __restrict__ C,
                  int M, int N, int K)
{
    __shared__ unsigned As[128][36];   // [m][k] row-major, pad 4
    __shared__ unsigned Bs[128][36];   // [n][k] row-major, pad 4
    const int t = threadIdx.x, lane = t & 31, w = t >> 5;
    const int m0 = blockIdx.y * 128, n0 = blockIdx.x * 128;
    const int wm = (w & 1) * 64, wn = (w >> 1) * 32;
    const int g = lane >> 2, qt = lane & 3;

    float acc[4][4][4];
#pragma unroll
    for (int i = 0; i < 4; i++)
#pragma unroll
        for (int j = 0; j < 4; j++)
#pragma unroll
            for (int r = 0; r < 4; r++) acc[i][j][r] = 0.f;

    for (int k0 = 0; k0 < K; k0 += 32) {
#pragma unroll
        for (int p = 0; p < 4; p++) {
            int linear = p * 1024 + t * 4;
            int r = linear >> 5, c = linear & 31;
            float4 av = *(const float4*)(A + (size_t)(m0 + r) * K + k0 + c);
            As[r][c] = f2tf(av.x); As[r][c+1] = f2tf(av.y);
            As[r][c+2] = f2tf(av.z); As[r][c+3] = f2tf(av.w);
            float4 bv = *(const float4*)(Bw + (size_t)(n0 + r) * K + k0 + c);
            Bs[r][c] = f2tf(bv.x); Bs[r][c+1] = f2tf(bv.y);
            Bs[r][c+2] = f2tf(bv.z); Bs[r][c+3] = f2tf(bv.w);
        }
        __syncthreads();
#pragma unroll
        for (int ks = 0; ks < 4; ks++) {
            unsigned af[4][4], bf[4][2];
            const int kc = ks * 8 + qt;
#pragma unroll
            for (int mt = 0; mt < 4; mt++) {
                const int mr = wm + mt * 16 + g;
                af[mt][0] = As[mr][kc];     af[mt][1] = As[mr+8][kc];
                af[mt][2] = As[mr][kc+4];   af[mt][3] = As[mr+8][kc+4];
            }
#pragma unroll
            for (int nt = 0; nt < 4; nt++) {
                const int nr = wn + nt * 8 + g;
                bf[nt][0] = Bs[nr][kc];     bf[nt][1] = Bs[nr][kc+4];
            }
#pragma unroll
            for (int mt = 0; mt < 4; mt++)
#pragma unroll
                for (int nt = 0; nt < 4; nt++)
                    mma8(acc[mt][nt], af[mt], bf[nt]);
        }
        __syncthreads();
    }

#pragma unroll
    for (int mt = 0; mt < 4; mt++) {
#pragma unroll
        for (int nt = 0; nt < 4; nt++) {
            const int n = n0 + wn + nt * 8 + 2 * qt;
            float b0 = bias ? bias[n] : 0.f;
            float b1 = bias ? bias[n+1] : 0.f;
#pragma unroll
            for (int rh = 0; rh < 2; rh++) {
                const int m = m0 + wm + mt * 16 + g + rh * 8;
                float v0 = acc[mt][nt][rh*2] + b0;
                float v1 = acc[mt][nt][rh*2+1] + b1;
                if (EPI == 0) {
                    *(float2*)(C + (size_t)m * N + n) = make_float2(v0, v1);
                } else {
                    int bi = m >> 11, mm = m & (M_ - 1);
                    int which = n >> 8, dd = n & 255;
                    int h = dd >> 5, c = dd & 31;
                    float* dst = (which == 0 ? g_q : which == 1 ? g_k : g_v)
                               + (size_t)(((bi << 3) + h) * M_ + mm) * DH_ + c;
                    *(float2*)dst = make_float2(v0, v1);
                }
            }
        }
    }
}

// ---------------- TN tf32 GEMM (split-K): S_partial = inc^T @ attnout ------
__global__ __launch_bounds__(256, 2)
void gemm_tn_S_tf32(const float* __restrict__ inc)
{
    __shared__ unsigned As[32][132];   // [token][e], pad 4
    __shared__ unsigned Bs[32][132];   // [token][d], pad 4
    const int t = threadIdx.x, lane = t & 31, w = t >> 5;
    const int z = blockIdx.z;
    const int b = z >> 2, sk = z & 3;
    const int e0 = blockIdx.y * 128, d0 = blockIdx.x * 128;
    const int kbase = sk * KCH;
    const int wm = (w & 1) * 64, wn = (w >> 1) * 32;
    const int g = lane >> 2, qt = lane & 3;
    const float* Ag = inc       + (size_t)b * M_ * E_;
    const float* Bg = g_attnout + (size_t)b * M_ * D_;

    float acc[4][4][4];
#pragma unroll
    for (int i = 0; i < 4; i++)
#pragma unroll
        for (int j = 0; j < 4; j++)
#pragma unroll
            for (int r = 0; r < 4; r++) acc[i][j][r] = 0.f;

    for (int k0 = 0; k0 < KCH; k0 += 32) {
#pragma unroll
        for (int p = 0; p < 4; p++) {
            int linear = p * 1024 + t * 4;
            int r = linear >> 7, c = linear & 127;
            int krow = kbase + k0 + r;
            float4 av = *(const float4*)(Ag + (size_t)krow * E_ + e0 + c);
            As[r][c] = f2tf(av.x); As[r][c+1] = f2tf(av.y);
            As[r][c+2] = f2tf(av.z); As[r][c+3] = f2tf(av.w);
            float4 bv = *(const float4*)(Bg + (size_t)krow * D_ + d0 + c);
            Bs[r][c] = f2tf(bv.x); Bs[r][c+1] = f2tf(bv.y);
            Bs[r][c+2] = f2tf(bv.z); Bs[r][c+3] = f2tf(bv.w);
        }
        __syncthreads();
#pragma unroll
        for (int ks = 0; ks < 4; ks++) {
            unsigned af[4][4], bf[4][2];
            const int kc = ks * 8 + qt;
#pragma unroll
            for (int mt = 0; mt < 4; mt++) {
                const int mr = wm + mt * 16 + g;
                af[mt][0] = As[kc][mr];     af[mt][1] = As[kc][mr+8];
                af[mt][2] = As[kc+4][mr];   af[mt][3] = As[kc+4][mr+8];
            }
#pragma unroll
            for (int nt = 0; nt < 4; nt++) {
                const int nr = wn + nt * 8 + g;
                bf[nt][0] = Bs[kc][nr];     bf[nt][1] = Bs[kc+4][nr];
            }
#pragma unroll
            for (int mt = 0; mt < 4; mt++)
#pragma unroll
                for (int nt = 0; nt < 4; nt++)
                    mma8(acc[mt][nt], af[mt], bf[nt]);
        }
        __syncthreads();
    }

    float* Cp = g_Spart + (size_t)(sk * B_ + b) * E_ * D_;
#pragma unroll
    for (int mt = 0; mt < 4; mt++)
#pragma unroll
        for (int nt = 0; nt < 4; nt++) {
            const int d = d0 + wn + nt * 8 + 2 * qt;
#pragma unroll
            for (int rh = 0; rh < 2; rh++) {
                const int e = e0 + wm + mt * 16 + g + rh * 8;
                *(float2*)(Cp + (size_t)e * D_ + d) =
                    make_float2(acc[mt][nt][rh*2], acc[mt][nt][rh*2+1]);
            }
        }
}

// ---------------- tensor-core flash attention (tf32 mma) -------------------
// grid (16 q-tiles, 32 bh), block 128 (4 warps). Warp owns 32 q rows.
#define FTK 64
#define KV_STRIDE 36
#define P_STRIDE 68
#define FLASH_SMEM ((2*FTK*KV_STRIDE + 4*32*P_STRIDE) * 4)

__global__ __launch_bounds__(128, 2)
void flash_attn_tf32()
{
    extern __shared__ unsigned smem[];
    unsigned* Ks = smem;                        // [64][36]
    unsigned* Vs = Ks + FTK * KV_STRIDE;        // [64][36]
    unsigned* Psw;                              // per-warp [32][68]

    const int t = threadIdx.x, lane = t & 31, w = t >> 5;
    const int g = lane >> 2, qt = lane & 3;
    const int bh = blockIdx.y;
    const int qbase = blockIdx.x * 128 + w * 32;
    Psw = Vs + FTK * KV_STRIDE + w * 32 * P_STRIDE;

    const float scale = 0.17677669529663687f;   // 1/sqrt(32)
    const float* qp = g_q + ((size_t)bh * M_ + qbase) * DH_;

    unsigned qf[2][4][4];
#pragma unroll
    for (int mt = 0; mt < 2; mt++)
#pragma unroll
        for (int ks = 0; ks < 4; ks++) {
            int r0 = mt * 16 + g, c0 = ks * 8 + qt;
            qf[mt][ks][0] = f2tf(scale * qp[r0*32 + c0]);
            qf[mt][ks][1] = f2tf(scale * qp[(r0+8)*32 + c0]);
            qf[mt][ks][2] = f2tf(scale * qp[r0*32 + c0 + 4]);
            qf[mt][ks][3] = f2tf(scale * qp[(r0+8)*32 + c0 + 4]);
        }

    float of[2][4][4];
#pragma unroll
    for (int i = 0; i < 2; i++)
#pragma unroll
        for (int j = 0; j < 4; j++)
#pragma unroll
            for (int r = 0; r < 4; r++) of[i][j][r] = 0.f;
    float mr[2][2] = {{-1e30f,-1e30f},{-1e30f,-1e30f}};
    float lr[2][2] = {{0.f,0.f},{0.f,0.f}};

    const float* kb = g_k + (size_t)bh * M_ * DH_;
    const float* vb = g_v + (size_t)bh * M_ * DH_;

    for (int kt = 0; kt < M_; kt += FTK) {
        __syncthreads();
#pragma unroll
        for (int p = 0; p < 4; p++) {
            int linear = p * 512 + t * 4;
            int r = linear >> 5, c = linear & 31;
            float4 kv = *(const float4*)(kb + (size_t)(kt + r) * DH_ + c);
            Ks[r*KV_STRIDE + c]   = f2tf(kv.x); Ks[r*KV_STRIDE + c+1] = f2tf(kv.y);
            Ks[r*KV_STRIDE + c+2] = f2tf(kv.z); Ks[r*KV_STRIDE + c+3] = f2tf(kv.w);
            float4 vv = *(const float4*)(vb + (size_t)(kt + r) * DH_ + c);
            Vs[r*KV_STRIDE + c]   = f2tf(vv.x); Vs[r*KV_STRIDE + c+1] = f2tf(vv.y);
            Vs[r*KV_STRIDE + c+2] = f2tf(vv.z); Vs[r*KV_STRIDE + c+3] = f2tf(vv.w);
        }
        __syncthreads();

        // S = Q @ K^T  (per warp: 32q x 64keys)
        float sf[2][8][4];
#pragma unroll
        for (int i = 0; i < 2; i++)
#pragma unroll
            for (int j = 0; j < 8; j++)
#pragma unroll
                for (int r = 0; r < 4; r++) sf[i][j][r] = 0.f;
#pragma unroll
        for (int ks = 0; ks < 4; ks++) {
            unsigned bf[8][2];
            const int kc = ks * 8 + qt;
#pragma unroll
            for (int n = 0; n < 8; n++) {
                bf[n][0] = Ks[(n*8 + g)*KV_STRIDE + kc];
                bf[n][1] = Ks[(n*8 + g)*KV_STRIDE + kc + 4];
            }
#pragma unroll
            for (int mt = 0; mt < 2; mt++)
#pragma unroll
                for (int n = 0; n < 8; n++)
                    mma8(sf[mt][n], qf[mt][ks], bf[n]);
        }

        // online softmax on fragments; P -> warp-private smem (tf32)
#pragma unroll
        for (int mt = 0; mt < 2; mt++) {
#pragma unroll
            for (int rh = 0; rh < 2; rh++) {
                float mx = -1e30f;
#pragma unroll
                for (int n = 0; n < 8; n++) {
                    mx = fmaxf(mx, sf[mt][n][rh*2]);
                    mx = fmaxf(mx, sf[mt][n][rh*2+1]);
                }
                mx = fmaxf(mx, __shfl_xor_sync(~0u, mx, 1));
                mx = fmaxf(mx, __shfl_xor_sync(~0u, mx, 2));
                float mn = fmaxf(mr[mt][rh], mx);
                float corr = __expf(mr[mt][rh] - mn);
                mr[mt][rh] = mn;
                lr[mt][rh] *= corr;
#pragma unroll
                for (int nd = 0; nd < 4; nd++) {
                    of[mt][nd][rh*2]   *= corr;
                    of[mt][nd][rh*2+1] *= corr;
                }
                float ls = 0.f;
                const int prow = (mt*16 + g + rh*8) * P_STRIDE;
#pragma unroll
                for (int n = 0; n < 8; n++) {
                    float e0 = __expf(sf[mt][n][rh*2]   - mn);
                    float e1 = __expf(sf[mt][n][rh*2+1] - mn);
                    ls += e0 + e1;
                    Psw[prow + n*8 + 2*qt]     = f2tf(e0);
                    Psw[prow + n*8 + 2*qt + 1] = f2tf(e1);
                }
                lr[mt][rh] += ls;
            }
        }
        __syncwarp();

        // O += P @ V  (32q x 64k @ 64k x 32d)
#pragma unroll
        for (int ks = 0; ks < 8; ks++) {
            unsigned af[2][4], bf[4][2];
            const int kc = ks * 8 + qt;
#pragma unroll
            for (int mt = 0; mt < 2; mt++) {
                const int r0 = (mt*16 + g) * P_STRIDE;
                af[mt][0] = Psw[r0 + kc];
                af[mt][1] = Psw[r0 + 8*P_STRIDE + kc];
                af[mt][2] = Psw[r0 + kc + 4];
                af[mt][3] = Psw[r0 + 8*P_STRIDE + kc + 4];
            }
#pragma unroll
            for (int nd = 0; nd < 4; nd++) {
                bf[nd][0] = Vs[kc*KV_STRIDE + nd*8 + g];
                bf[nd][1] = Vs[(kc+4)*KV_STRIDE + nd*8 + g];
            }
#pragma unroll
            for (int mt = 0; mt < 2; mt++)
#pragma unroll
                for (int nd = 0; nd < 4; nd++)
                    mma8(of[mt][nd], af[mt], bf[nd]);
        }
    }

    // finalize + store into g_attn [b][m][h*32 + d]
    const int b = bh >> 3, h = bh & 7;
#pragma unroll
    for (int mt = 0; mt < 2; mt++)
#pragma unroll
        for (int rh = 0; rh < 2; rh++) {
            float l = lr[mt][rh];
            l += __shfl_xor_sync(~0u, l, 1);
            l += __shfl_xor_sync(~0u, l, 2);
            float inv = 1.f / l;
            const int q = qbase + mt*16 + g + rh*8;
            float* op = g_attn + ((size_t)b * M_ + q) * D_ + h * DH_;
#pragma unroll
            for (int nd = 0; nd < 4; nd++)
                *(float2*)(op + nd*8 + 2*qt) =
                    make_float2(of[mt][nd][rh*2]*inv, of[mt][nd][rh*2+1]*inv);
        }
}

// ---------------- fused split-K reduce + column softmax (coalesced) --------
// pass1: reduce 4 partials -> g_S, online (max,sum) per (b,d) over e-chunk
__global__ void sm_pass1()
{
    const int b = blockIdx.y, ec = blockIdx.x, d = threadIdx.x;
    const size_t NB = (size_t)B_*E_*D_;
    size_t off = ((size_t)b*E_ + ec*ECH)*D_ + d;
    float m = -1e30f, l = 0.f;
    for (int e = 0; e < ECH; e++) {
        size_t idx = off + (size_t)e*D_;
        float s = g_Spart[idx] + g_Spart[idx+NB] + g_Spart[idx+2*NB] + g_Spart[idx+3*NB];
        g_S[idx] = s;
        float mn = fmaxf(m, s);
        l = l*__expf(m - mn) + __expf(s - mn);
        m = mn;
    }
    g_m1[(b*ESPL + ec)*D_ + d] = m;
    g_l1[(b*ESPL + ec)*D_ + d] = l;
}
__global__ void sm_combine()
{
    const int b = blockIdx.x, d = threadIdx.x;
    float M = -1e30f, L = 0.f;
    for (int ec = 0; ec < ESPL; ec++) {
        float m = g_m1[(b*ESPL + ec)*D_ + d];
        float l = g_l1[(b*ESPL + ec)*D_ + d];
        float Mn = fmaxf(M, m);
        L = L*__expf(M - Mn) + l*__expf(m - Mn);
        M = Mn;
    }
    g_mg[b*D_ + d] = M;
    g_li[b*D_ + d] = 1.f / L;
}
__global__ void sm_pass2()
{
    const int b = blockIdx.y, ec = blockIdx.x, d = threadIdx.x;
    const float M = g_mg[b*D_ + d], Li = g_li[b*D_ + d];
    size_t off = ((size_t)b*E_ + ec*ECH)*D_ + d;
    for (int e = 0; e < ECH; e++) {
        size_t idx = off + (size_t)e*D_;
        float s = g_S[idx];
        g_ef[idx] = s * __expf(s - M) * Li;
    }
}

// ---------------- LayerNorm + residual -------------------------------------
__global__ void ln_residual(const float* __restrict__ prev,
                            const float* __restrict__ gamma,
                            const float* __restrict__ beta,
                            const float* __restrict__ alphap,
                            float* __restrict__ out)
{
    const int t = threadIdx.x, lane = t & 31, wid = t >> 5;
    const int row = blockIdx.x * 8 + wid;
    const float* x = g_ef2 + (size_t)row * D_;
    float xs[8], sum = 0.f, sq = 0.f;
#pragma unroll
    for (int c = 0; c < 8; c++) {
        float v = x[lane + c*32];
        xs[c] = v; sum += v; sq += v*v;
    }
#pragma unroll
    for (int off = 16; off; off >>= 1) {
        sum += __shfl_xor_sync(~0u, sum, off);
        sq  += __shfl_xor_sync(~0u, sq,  off);
    }
    const float mu   = sum * (1.f / D_);
    const float var  = sq * (1.f / D_) - mu * mu;
    const float rstd = rsqrtf(var + 1e-5f);
    const float alpha = *alphap;
#pragma unroll
    for (int c = 0; c < 8; c++) {
        int d = lane + c*32;
        float y = (xs[c] - mu) * rstd * gamma[d] + beta[d];
        size_t idx = (size_t)row * D_ + d;
        out[idx] = (1.f + alpha) * prev[idx] + (1.f - alpha) * y;
    }
}

// ---------------- launch ----------------------------------------------------
extern "C" void kernel_launch(void* const* d_in, const int* in_sizes, int n_in,
                              void* d_out, int out_size)
{
    const float* feature = (const float*)d_in[0];
    const float* inc     = (const float*)d_in[1];
    const float* prev    = (const float*)d_in[2];
    const float* inw     = (const float*)d_in[3];
    const float* inb     = (const float*)d_in[4];
    const float* outw    = (const float*)d_in[5];
    const float* outb    = (const float*)d_in[6];
    const float* projw   = (const float*)d_in[7];
    const float* gamma   = (const float*)d_in[8];
    const float* beta    = (const float*)d_in[9];
    const float* alphap  = (const float*)d_in[10];
    float* out = (float*)d_out;

    float *p_attn = 0, *p_attnout = 0, *p_ef = 0, *p_ef2 = 0;
    cudaGetSymbolAddress((void**)&p_attn,    g_attn);
    cudaGetSymbolAddress((void**)&p_attnout, g_attnout);
    cudaGetSymbolAddress((void**)&p_ef,      g_ef);
    cudaGetSymbolAddress((void**)&p_ef2,     g_ef2);

    cudaFuncSetAttribute(flash_attn_tf32,
                         cudaFuncAttributeMaxDynamicSharedMemorySize, FLASH_SMEM);

    // 1. QKV projection -> scatter to q/k/v
    gemm_nt_tf32<1><<<dim3(6, 64), 256>>>(feature, inw, inb, (float*)0, B_*M_, 3*D_, D_);
    // 2. attention (tensor cores)
    flash_attn_tf32<<<dim3(16, 32), 128, FLASH_SMEM>>>();
    // 3. out_proj
    gemm_nt_tf32<0><<<dim3(2, 64), 256>>>(p_attn, outw, outb, p_attnout, B_*M_, D_, D_);
    // 4. S = inc^T @ attnout (split-K partials)
    gemm_tn_S_tf32<<<dim3(2, 8, B_*SPLITK), 256>>>(inc);
    // 5. fused reduce + softmax over e + ef = S*W (coalesced)
    sm_pass1<<<dim3(ESPL, B_), 256>>>();
    sm_combine<<<B_, 256>>>();
    sm_pass2<<<dim3(ESPL, B_), 256>>>();
    // 6. final projection
    gemm_nt_tf32<0><<<dim3(2, 32), 256>>>(p_ef, projw, (float*)0, p_ef2, B_*E_, D_, D_);
    // 7. LN + residual mix
    ln_residual<<<512, 256>>>(prev, gamma, beta, alphap, out);
}

// round 10
// speedup vs baseline: 1.3458x; 1.0642x over previous
#include <cuda_runtime.h>
#include <math.h>

#define B_ 4
#define M_ 2048
#define E_ 1024
#define D_ 256
#define H_ 8
#define DH_ 32
#define SPLITK 4
#define KCH (M_ / SPLITK)   // 512

// ---------------- scratch (device globals: allocation-free) ----------------
__device__ float g_q[B_*H_*M_*DH_];
__device__ float g_k[B_*H_*M_*DH_];
__device__ float g_v[B_*H_*M_*DH_];
__device__ float g_attn[B_*M_*D_];
__device__ float g_attnout[B_*M_*D_];
__device__ float g_Spart[SPLITK*B_*E_*D_];
__device__ float g_S[B_*E_*D_];
__device__ float g_ef[B_*E_*D_];
__device__ float g_ef2[B_*E_*D_];

// ---------------- tf32 helpers ---------------------------------------------
__device__ __forceinline__ unsigned f2tf(float f) {
    unsigned u;
    asm("cvt.rna.tf32.f32 %0, %1;" : "=r"(u) : "f"(f));
    return u;
}
// D += A@B, m16n8k8 tf32
__device__ __forceinline__ void mma8(float* d, const unsigned* a, const unsigned* b) {
    asm volatile(
        "mma.sync.aligned.m16n8k8.row.col.f32.tf32.tf32.f32 "
        "{%0,%1,%2,%3},{%4,%5,%6,%7},{%8,%9},{%0,%1,%2,%3};"
        : "+f"(d[0]), "+f"(d[1]), "+f"(d[2]), "+f"(d[3])
        : "r"(a[0]), "r"(a[1]), "r"(a[2]), "r"(a[3]), "r"(b[0]), "r"(b[1]));
}

// ---------------- NT tf32 GEMM: C[M,N] = A[M,K] @ Bw[N,K]^T (+bias) --------
// 128x128x32 tile, 256 thr (8 warps 2x4), warp tile 64x32
// EPI==0: plain store. EPI==1: scatter into g_q/g_k/g_v [bh,m,dh].
template<int EPI>
__global__ __launch_bounds__(256, 2)
void gemm_nt_tf32(const float* __restrict__ A, const float* __restrict__ Bw,
                  const float* __restrict__ bias, float* __restrict__ C,
                  int M, int N, int K)
{
    __shared__ unsigned As[128][36];   // [m][k] row-major, pad 4
    __shared__ unsigned Bs[128][36];   // [n][k] row-major, pad 4
    const int t = threadIdx.x, lane = t & 31, w = t >> 5;
    const int m0 = blockIdx.y * 128, n0 = blockIdx.x * 128;
    const int wm = (w & 1) * 64, wn = (w >> 1) * 32;
    const int g = lane >> 2, qt = lane & 3;

    float acc[4][4][4];
#pragma unroll
    for (int i = 0; i < 4; i++)
#pragma unroll
        for (int j = 0; j < 4; j++)
#pragma unroll
            for (int r = 0; r < 4; r++) acc[i][j][r] = 0.f;

    for (int k0 = 0; k0 < K; k0 += 32) {
#pragma unroll
        for (int p = 0; p < 4; p++) {
            int linear = p * 1024 + t * 4;
            int r = linear >> 5, c = linear & 31;
            float4 av = *(const float4*)(A + (size_t)(m0 + r) * K + k0 + c);
            As[r][c] = f2tf(av.x); As[r][c+1] = f2tf(av.y);
            As[r][c+2] = f2tf(av.z); As[r][c+3] = f2tf(av.w);
            float4 bv = *(const float4*)(Bw + (size_t)(n0 + r) * K + k0 + c);
            Bs[r][c] = f2tf(bv.x); Bs[r][c+1] = f2tf(bv.y);
            Bs[r][c+2] = f2tf(bv.z); Bs[r][c+3] = f2tf(bv.w);
        }
        __syncthreads();
#pragma unroll
        for (int ks = 0; ks < 4; ks++) {
            unsigned af[4][4], bf[4][2];
            const int kc = ks * 8 + qt;
#pragma unroll
            for (int mt = 0; mt < 4; mt++) {
                const int mr = wm + mt * 16 + g;
                af[mt][0] = As[mr][kc];     af[mt][1] = As[mr+8][kc];
                af[mt][2] = As[mr][kc+4];   af[mt][3] = As[mr+8][kc+4];
            }
#pragma unroll
            for (int nt = 0; nt < 4; nt++) {
                const int nr = wn + nt * 8 + g;
                bf[nt][0] = Bs[nr][kc];     bf[nt][1] = Bs[nr][kc+4];
            }
#pragma unroll
            for (int mt = 0; mt < 4; mt++)
#pragma unroll
                for (int nt = 0; nt < 4; nt++)
                    mma8(acc[mt][nt], af[mt], bf[nt]);
        }
        __syncthreads();
    }

#pragma unroll
    for (int mt = 0; mt < 4; mt++) {
#pragma unroll
        for (int nt = 0; nt < 4; nt++) {
            const int n = n0 + wn + nt * 8 + 2 * qt;
            float b0 = bias ? bias[n] : 0.f;
            float b1 = bias ? bias[n+1] : 0.f;
#pragma unroll
            for (int rh = 0; rh < 2; rh++) {
                const int m = m0 + wm + mt * 16 + g + rh * 8;
                float v0 = acc[mt][nt][rh*2] + b0;
                float v1 = acc[mt][nt][rh*2+1] + b1;
                if (EPI == 0) {
                    *(float2*)(C + (size_t)m * N + n) = make_float2(v0, v1);
                } else {
                    int bi = m >> 11, mm = m & (M_ - 1);
                    int which = n >> 8, dd = n & 255;
                    int h = dd >> 5, c = dd & 31;
                    float* dst = (which == 0 ? g_q : which == 1 ? g_k : g_v)
                               + (size_t)(((bi << 3) + h) * M_ + mm) * DH_ + c;
                    *(float2*)dst = make_float2(v0, v1);
                }
            }
        }
    }
}

// ---------------- TN tf32 GEMM (split-K): S_partial = inc^T @ attnout ------
__global__ __launch_bounds__(256, 2)
void gemm_tn_S_tf32(const float* __restrict__ inc)
{
    __shared__ unsigned As[32][132];   // [token][e], pad 4
    __shared__ unsigned Bs[32][132];   // [token][d], pad 4
    const int t = threadIdx.x, lane = t & 31, w = t >> 5;
    const int z = blockIdx.z;
    const int b = z >> 2, sk = z & 3;
    const int e0 = blockIdx.y * 128, d0 = blockIdx.x * 128;
    const int kbase = sk * KCH;
    const int wm = (w & 1) * 64, wn = (w >> 1) * 32;
    const int g = lane >> 2, qt = lane & 3;
    const float* Ag = inc       + (size_t)b * M_ * E_;
    const float* Bg = g_attnout + (size_t)b * M_ * D_;

    float acc[4][4][4];
#pragma unroll
    for (int i = 0; i < 4; i++)
#pragma unroll
        for (int j = 0; j < 4; j++)
#pragma unroll
            for (int r = 0; r < 4; r++) acc[i][j][r] = 0.f;

    for (int k0 = 0; k0 < KCH; k0 += 32) {
#pragma unroll
        for (int p = 0; p < 4; p++) {
            int linear = p * 1024 + t * 4;
            int r = linear >> 7, c = linear & 127;
            int krow = kbase + k0 + r;
            float4 av = *(const float4*)(Ag + (size_t)krow * E_ + e0 + c);
            As[r][c] = f2tf(av.x); As[r][c+1] = f2tf(av.y);
            As[r][c+2] = f2tf(av.z); As[r][c+3] = f2tf(av.w);
            float4 bv = *(const float4*)(Bg + (size_t)krow * D_ + d0 + c);
            Bs[r][c] = f2tf(bv.x); Bs[r][c+1] = f2tf(bv.y);
            Bs[r][c+2] = f2tf(bv.z); Bs[r][c+3] = f2tf(bv.w);
        }
        __syncthreads();
#pragma unroll
        for (int ks = 0; ks < 4; ks++) {
            unsigned af[4][4], bf[4][2];
            const int kc = ks * 8 + qt;
#pragma unroll
            for (int mt = 0; mt < 4; mt++) {
                const int mr = wm + mt * 16 + g;
                af[mt][0] = As[kc][mr];     af[mt][1] = As[kc][mr+8];
                af[mt][2] = As[kc+4][mr];   af[mt][3] = As[kc+4][mr+8];
            }
#pragma unroll
            for (int nt = 0; nt < 4; nt++) {
                const int nr = wn + nt * 8 + g;
                bf[nt][0] = Bs[kc][nr];     bf[nt][1] = Bs[kc+4][nr];
            }
#pragma unroll
            for (int mt = 0; mt < 4; mt++)
#pragma unroll
                for (int nt = 0; nt < 4; nt++)
                    mma8(acc[mt][nt], af[mt], bf[nt]);
        }
        __syncthreads();
    }

    float* Cp = g_Spart + (size_t)(sk * B_ + b) * E_ * D_;
#pragma unroll
    for (int mt = 0; mt < 4; mt++)
#pragma unroll
        for (int nt = 0; nt < 4; nt++) {
            const int d = d0 + wn + nt * 8 + 2 * qt;
#pragma unroll
            for (int rh = 0; rh < 2; rh++) {
                const int e = e0 + wm + mt * 16 + g + rh * 8;
                *(float2*)(Cp + (size_t)e * D_ + d) =
                    make_float2(acc[mt][nt][rh*2], acc[mt][nt][rh*2+1]);
            }
        }
}

// deterministic split-K reduction (R2 version: high MLP, full grid)
__global__ void reduce_S()
{
    const int i = blockIdx.x * 256 + threadIdx.x;
    const int N4 = B_*E_*D_/4;
    const float4* p = (const float4*)g_Spart;
    float4 a = p[i], b = p[i + N4], c = p[i + 2*N4], d = p[i + 3*N4];
    ((float4*)g_S)[i] = make_float4(a.x+b.x+c.x+d.x, a.y+b.y+c.y+d.y,
                                    a.z+b.z+c.z+d.z, a.w+b.w+c.w+d.w);
}

// ---------------- tensor-core flash attention (tf32 mma, shuffle PV) -------
// grid (16 q-tiles, 32 bh), block 128 (4 warps). Warp owns 32 q rows.
// P never touches smem: S-acc fragments are permuted to A-operand layout
// with quad shuffles. Smem = K/V tiles only (18 KB) -> 3 blocks/SM.
#define FTK 64
#define KV_STRIDE 36

__global__ __launch_bounds__(128, 3)
void flash_attn_tf32()
{
    __shared__ unsigned Ks[FTK*KV_STRIDE];
    __shared__ unsigned Vs[FTK*KV_STRIDE];

    const int t = threadIdx.x, lane = t & 31, w = t >> 5;
    const int g = lane >> 2, qt = lane & 3;
    const int bh = blockIdx.y;
    const int qbase = blockIdx.x * 128 + w * 32;

    const float scale = 0.17677669529663687f;   // 1/sqrt(32)
    const float* qp = g_q + ((size_t)bh * M_ + qbase) * DH_;

    unsigned qf[2][4][4];
#pragma unroll
    for (int mt = 0; mt < 2; mt++)
#pragma unroll
        for (int ks = 0; ks < 4; ks++) {
            int r0 = mt * 16 + g, c0 = ks * 8 + qt;
            qf[mt][ks][0] = f2tf(scale * qp[r0*32 + c0]);
            qf[mt][ks][1] = f2tf(scale * qp[(r0+8)*32 + c0]);
            qf[mt][ks][2] = f2tf(scale * qp[r0*32 + c0 + 4]);
            qf[mt][ks][3] = f2tf(scale * qp[(r0+8)*32 + c0 + 4]);
        }

    float of[2][4][4];
#pragma unroll
    for (int i = 0; i < 2; i++)
#pragma unroll
        for (int j = 0; j < 4; j++)
#pragma unroll
            for (int r = 0; r < 4; r++) of[i][j][r] = 0.f;
    float mr[2][2] = {{-1e30f,-1e30f},{-1e30f,-1e30f}};
    float lr[2][2] = {{0.f,0.f},{0.f,0.f}};

    const float* kb = g_k + (size_t)bh * M_ * DH_;
    const float* vb = g_v + (size_t)bh * M_ * DH_;

    const int srcA = (lane & ~3) | (qt >> 1);
    const int srcB = srcA | 2;
    const bool odd = qt & 1;

    for (int kt = 0; kt < M_; kt += FTK) {
        __syncthreads();
#pragma unroll
        for (int p = 0; p < 4; p++) {
            int linear = p * 512 + t * 4;
            int r = linear >> 5, c = linear & 31;
            float4 kv = *(const float4*)(kb + (size_t)(kt + r) * DH_ + c);
            Ks[r*KV_STRIDE + c]   = f2tf(kv.x); Ks[r*KV_STRIDE + c+1] = f2tf(kv.y);
            Ks[r*KV_STRIDE + c+2] = f2tf(kv.z); Ks[r*KV_STRIDE + c+3] = f2tf(kv.w);
            float4 vv = *(const float4*)(vb + (size_t)(kt + r) * DH_ + c);
            Vs[r*KV_STRIDE + c]   = f2tf(vv.x); Vs[r*KV_STRIDE + c+1] = f2tf(vv.y);
            Vs[r*KV_STRIDE + c+2] = f2tf(vv.z); Vs[r*KV_STRIDE + c+3] = f2tf(vv.w);
        }
        __syncthreads();

        // S = Q @ K^T  (per warp: 32q x 64keys)
        float sf[2][8][4];
#pragma unroll
        for (int i = 0; i < 2; i++)
#pragma unroll
            for (int j = 0; j < 8; j++)
#pragma unroll
                for (int r = 0; r < 4; r++) sf[i][j][r] = 0.f;
#pragma unroll
        for (int ks = 0; ks < 4; ks++) {
            unsigned bfk[8][2];
            const int kc = ks * 8 + qt;
#pragma unroll
            for (int n = 0; n < 8; n++) {
                bfk[n][0] = Ks[(n*8 + g)*KV_STRIDE + kc];
                bfk[n][1] = Ks[(n*8 + g)*KV_STRIDE + kc + 4];
            }
#pragma unroll
            for (int mt = 0; mt < 2; mt++)
#pragma unroll
                for (int n = 0; n < 8; n++)
                    mma8(sf[mt][n], qf[mt][ks], bfk[n]);
        }

        // online softmax on fragments; overwrite sf with exp values
#pragma unroll
        for (int mt = 0; mt < 2; mt++) {
#pragma unroll
            for (int rh = 0; rh < 2; rh++) {
                float mx = -1e30f;
#pragma unroll
                for (int n = 0; n < 8; n++) {
                    mx = fmaxf(mx, sf[mt][n][rh*2]);
                    mx = fmaxf(mx, sf[mt][n][rh*2+1]);
                }
                mx = fmaxf(mx, __shfl_xor_sync(~0u, mx, 1));
                mx = fmaxf(mx, __shfl_xor_sync(~0u, mx, 2));
                float mn = fmaxf(mr[mt][rh], mx);
                float corr = __expf(mr[mt][rh] - mn);
                mr[mt][rh] = mn;
                lr[mt][rh] *= corr;
#pragma unroll
                for (int nd = 0; nd < 4; nd++) {
                    of[mt][nd][rh*2]   *= corr;
                    of[mt][nd][rh*2+1] *= corr;
                }
                float ls = 0.f;
#pragma unroll
                for (int n = 0; n < 8; n++) {
                    float e0 = __expf(sf[mt][n][rh*2]   - mn);
                    float e1 = __expf(sf[mt][n][rh*2+1] - mn);
                    ls += e0 + e1;
                    sf[mt][n][rh*2] = e0; sf[mt][n][rh*2+1] = e1;
                }
                lr[mt][rh] += ls;
            }
        }

        // O += P @ V : permute acc fragments -> A layout via quad shuffles
#pragma unroll
        for (int ks = 0; ks < 8; ks++) {
            unsigned bfv[4][2];
            const int kc = ks * 8 + qt;
#pragma unroll
            for (int nd = 0; nd < 4; nd++) {
                bfv[nd][0] = Vs[kc*KV_STRIDE + nd*8 + g];
                bfv[nd][1] = Vs[(kc+4)*KV_STRIDE + nd*8 + g];
            }
#pragma unroll
            for (int mt = 0; mt < 2; mt++) {
                float aA0 = __shfl_sync(~0u, sf[mt][ks][0], srcA);
                float aA1 = __shfl_sync(~0u, sf[mt][ks][1], srcA);
                float aA2 = __shfl_sync(~0u, sf[mt][ks][2], srcA);
                float aA3 = __shfl_sync(~0u, sf[mt][ks][3], srcA);
                float aB0 = __shfl_sync(~0u, sf[mt][ks][0], srcB);
                float aB1 = __shfl_sync(~0u, sf[mt][ks][1], srcB);
                float aB2 = __shfl_sync(~0u, sf[mt][ks][2], srcB);
                float aB3 = __shfl_sync(~0u, sf[mt][ks][3], srcB);
                unsigned af[4];
                af[0] = f2tf(odd ? aA1 : aA0);   // [g][qt]
                af[1] = f2tf(odd ? aA3 : aA2);   // [g+8][qt]
                af[2] = f2tf(odd ? aB1 : aB0);   // [g][qt+4]
                af[3] = f2tf(odd ? aB3 : aB2);   // [g+8][qt+4]
#pragma unroll
                for (int nd = 0; nd < 4; nd++)
                    mma8(of[mt][nd], af, bfv[nd]);
            }
        }
    }

    // finalize + store into g_attn [b][m][h*32 + d]
    const int b = bh >> 3, h = bh & 7;
#pragma unroll
    for (int mt = 0; mt < 2; mt++)
#pragma unroll
        for (int rh = 0; rh < 2; rh++) {
            float l = lr[mt][rh];
            l += __shfl_xor_sync(~0u, l, 1);
            l += __shfl_xor_sync(~0u, l, 2);
            float inv = 1.f / l;
            const int q = qbase + mt*16 + g + rh*8;
            float* op = g_attn + ((size_t)b * M_ + q) * D_ + h * DH_;
#pragma unroll
            for (int nd = 0; nd < 4; nd++)
                *(float2*)(op + nd*8 + 2*qt) =
                    make_float2(of[mt][nd][rh*2]*inv, of[mt][nd][rh*2+1]*inv);
        }
}

// ---------------- softmax over hyperedge dim + ef = S*W (R2 version) -------
__global__ void softmax_e()
{
    const int t = threadIdx.x, lane = t & 31, wid = t >> 5;
    const int col = blockIdx.x * 8 + wid;
    const int b = col >> 8, d = col & 255;
    const float* base = g_S + (size_t)b * E_ * D_ + d;
    float v[32];
    float mx = -1e30f;
#pragma unroll
    for (int r = 0; r < 32; r++) {
        float x = base[(size_t)(lane + r*32) * D_];
        v[r] = x; mx = fmaxf(mx, x);
    }
#pragma unroll
    for (int off = 16; off; off >>= 1) mx = fmaxf(mx, __shfl_xor_sync(~0u, mx, off));
    float se = 0.f;
#pragma unroll
    for (int r = 0; r < 32; r++) se += __expf(v[r] - mx);
#pragma unroll
    for (int off = 16; off; off >>= 1) se += __shfl_xor_sync(~0u, se, off);
    float inv = 1.f / se;
    float* ob = g_ef + (size_t)b * E_ * D_ + d;
#pragma unroll
    for (int r = 0; r < 32; r++)
        ob[(size_t)(lane + r*32) * D_] = v[r] * __expf(v[r] - mx) * inv;
}

// ---------------- LayerNorm + residual -------------------------------------
__global__ void ln_residual(const float* __restrict__ prev,
                            const float* __restrict__ gamma,
                            const float* __restrict__ beta,
                            const float* __restrict__ alphap,
                            float* __restrict__ out)
{
    const int t = threadIdx.x, lane = t & 31, wid = t >> 5;
    const int row = blockIdx.x * 8 + wid;
    const float* x = g_ef2 + (size_t)row * D_;
    float xs[8], sum = 0.f, sq = 0.f;
#pragma unroll
    for (int c = 0; c < 8; c++) {
        float v = x[lane + c*32];
        xs[c] = v; sum += v; sq += v*v;
    }
#pragma unroll
    for (int off = 16; off; off >>= 1) {
        sum += __shfl_xor_sync(~0u, sum, off);
        sq  += __shfl_xor_sync(~0u, sq,  off);
    }
    const float mu   = sum * (1.f / D_);
    const float var  = sq * (1.f / D_) - mu * mu;
    const float rstd = rsqrtf(var + 1e-5f);
    const float alpha = *alphap;
#pragma unroll
    for (int c = 0; c < 8; c++) {
        int d = lane + c*32;
        float y = (xs[c] - mu) * rstd * gamma[d] + beta[d];
        size_t idx = (size_t)row * D_ + d;
        out[idx] = (1.f + alpha) * prev[idx] + (1.f - alpha) * y;
    }
}

// ---------------- launch ----------------------------------------------------
extern "C" void kernel_launch(void* const* d_in, const int* in_sizes, int n_in,
                              void* d_out, int out_size)
{
    const float* feature = (const float*)d_in[0];
    const float* inc     = (const float*)d_in[1];
    const float* prev    = (const float*)d_in[2];
    const float* inw     = (const float*)d_in[3];
    const float* inb     = (const float*)d_in[4];
    const float* outw    = (const float*)d_in[5];
    const float* outb    = (const float*)d_in[6];
    const float* projw   = (const float*)d_in[7];
    const float* gamma   = (const float*)d_in[8];
    const float* beta    = (const float*)d_in[9];
    const float* alphap  = (const float*)d_in[10];
    float* out = (float*)d_out;

    float *p_attn = 0, *p_attnout = 0, *p_ef = 0, *p_ef2 = 0;
    cudaGetSymbolAddress((void**)&p_attn,    g_attn);
    cudaGetSymbolAddress((void**)&p_attnout, g_attnout);
    cudaGetSymbolAddress((void**)&p_ef,      g_ef);
    cudaGetSymbolAddress((void**)&p_ef2,     g_ef2);

    // 1. QKV projection -> scatter to q/k/v
    gemm_nt_tf32<1><<<dim3(6, 64), 256>>>(feature, inw, inb, (float*)0, B_*M_, 3*D_, D_);
    // 2. attention (tensor cores, shuffle-PV, 18KB smem)
    flash_attn_tf32<<<dim3(16, 32), 128>>>();
    // 3. out_proj
    gemm_nt_tf32<0><<<dim3(2, 64), 256>>>(p_attn, outw, outb, p_attnout, B_*M_, D_, D_);
    // 4. S = inc^T @ attnout (split-K partials) + reduce
    gemm_tn_S_tf32<<<dim3(2, 8, B_*SPLITK), 256>>>(inc);
    reduce_S<<<B_*E_*D_/4/256, 256>>>();
    // 5. softmax over e + ef = S*W
    softmax_e<<<128, 256>>>();
    // 6. final projection
    gemm_nt_tf32<0><<<dim3(2, 32), 256>>>(p_ef, projw, (float*)0, p_ef2, B_*E_, D_, D_);
    // 7. LN + residual mix
    ln_residual<<<512, 256>>>(prev, gamma, beta, alphap, out);
}

// round 12
// speedup vs baseline: 1.5777x; 1.1723x over previous
#include <cuda_runtime.h>
#include <math.h>

#define B_ 4
#define M_ 2048
#define E_ 1024
#define D_ 256
#define H_ 8
#define DH_ 32
#define SPLITK 4
#define KCH (M_ / SPLITK)   // 512

// ---------------- scratch (device globals: allocation-free) ----------------
__device__ float g_q[B_*H_*M_*DH_];
__device__ float g_k[B_*H_*M_*DH_];
__device__ float g_v[B_*H_*M_*DH_];
__device__ float g_attn[B_*M_*D_];
__device__ float g_attnout[B_*M_*D_];
__device__ float g_Spart[SPLITK*B_*E_*D_];
__device__ float g_S[B_*E_*D_];
__device__ float g_ef[B_*E_*D_];
__device__ float g_ef2[B_*E_*D_];

// ---------------- helpers ---------------------------------------------------
__device__ __forceinline__ unsigned f2tf(float f) {
    unsigned u;
    asm("cvt.rna.tf32.f32 %0, %1;" : "=r"(u) : "f"(f));
    return u;
}
// D += A@B, m16n8k8 tf32
__device__ __forceinline__ void mma8(float* d, const unsigned* a, const unsigned* b) {
    asm volatile(
        "mma.sync.aligned.m16n8k8.row.col.f32.tf32.tf32.f32 "
        "{%0,%1,%2,%3},{%4,%5,%6,%7},{%8,%9},{%0,%1,%2,%3};"
        : "+f"(d[0]), "+f"(d[1]), "+f"(d[2]), "+f"(d[3])
        : "r"(a[0]), "r"(a[1]), "r"(a[2]), "r"(a[3]), "r"(b[0]), "r"(b[1]));
}
// D += A@B, m16n8k16 fp16 in, fp32 accum
__device__ __forceinline__ void mma16(float* d, const unsigned* a, const unsigned* b) {
    asm volatile(
        "mma.sync.aligned.m16n8k16.row.col.f32.f16.f16.f32 "
        "{%0,%1,%2,%3},{%4,%5,%6,%7},{%8,%9},{%0,%1,%2,%3};"
        : "+f"(d[0]), "+f"(d[1]), "+f"(d[2]), "+f"(d[3])
        : "r"(a[0]), "r"(a[1]), "r"(a[2]), "r"(a[3]), "r"(b[0]), "r"(b[1]));
}
// pack two f32 -> f16x2 (lo = first elem)
__device__ __forceinline__ unsigned pk16(float lo, float hi) {
    unsigned r;
    asm("cvt.rn.f16x2.f32 %0, %1, %2;" : "=r"(r) : "f"(hi), "f"(lo));
    return r;
}

// ---------------- NT tf32 GEMM: C[M,N] = A[M,K] @ Bw[N,K]^T (+bias) --------
template<int EPI>
__global__ __launch_bounds__(256, 2)
void gemm_nt_tf32(const float* __restrict__ A, const float* __restrict__ Bw,
                  const float* __restrict__ bias, float* __restrict__ C,
                  int M, int N, int K)
{
    __shared__ unsigned As[128][36];
    __shared__ unsigned Bs[128][36];
    const int t = threadIdx.x, lane = t & 31, w = t >> 5;
    const int m0 = blockIdx.y * 128, n0 = blockIdx.x * 128;
    const int wm = (w & 1) * 64, wn = (w >> 1) * 32;
    const int g = lane >> 2, qt = lane & 3;

    float acc[4][4][4];
#pragma unroll
    for (int i = 0; i < 4; i++)
#pragma unroll
        for (int j = 0; j < 4; j++)
#pragma unroll
            for (int r = 0; r < 4; r++) acc[i][j][r] = 0.f;

    for (int k0 = 0; k0 < K; k0 += 32) {
#pragma unroll
        for (int p = 0; p < 4; p++) {
            int linear = p * 1024 + t * 4;
            int r = linear >> 5, c = linear & 31;
            float4 av = *(const float4*)(A + (size_t)(m0 + r) * K + k0 + c);
            As[r][c] = f2tf(av.x); As[r][c+1] = f2tf(av.y);
            As[r][c+2] = f2tf(av.z); As[r][c+3] = f2tf(av.w);
            float4 bv = *(const float4*)(Bw + (size_t)(n0 + r) * K + k0 + c);
            Bs[r][c] = f2tf(bv.x); Bs[r][c+1] = f2tf(bv.y);
            Bs[r][c+2] = f2tf(bv.z); Bs[r][c+3] = f2tf(bv.w);
        }
        __syncthreads();
#pragma unroll
        for (int ks = 0; ks < 4; ks++) {
            unsigned af[4][4], bf[4][2];
            const int kc = ks * 8 + qt;
#pragma unroll
            for (int mt = 0; mt < 4; mt++) {
                const int mr = wm + mt * 16 + g;
                af[mt][0] = As[mr][kc];     af[mt][1] = As[mr+8][kc];
                af[mt][2] = As[mr][kc+4];   af[mt][3] = As[mr+8][kc+4];
            }
#pragma unroll
            for (int nt = 0; nt < 4; nt++) {
                const int nr = wn + nt * 8 + g;
                bf[nt][0] = Bs[nr][kc];     bf[nt][1] = Bs[nr][kc+4];
            }
#pragma unroll
            for (int mt = 0; mt < 4; mt++)
#pragma unroll
                for (int nt = 0; nt < 4; nt++)
                    mma8(acc[mt][nt], af[mt], bf[nt]);
        }
        __syncthreads();
    }

#pragma unroll
    for (int mt = 0; mt < 4; mt++) {
#pragma unroll
        for (int nt = 0; nt < 4; nt++) {
            const int n = n0 + wn + nt * 8 + 2 * qt;
            float b0 = bias ? bias[n] : 0.f;
            float b1 = bias ? bias[n+1] : 0.f;
#pragma unroll
            for (int rh = 0; rh < 2; rh++) {
                const int m = m0 + wm + mt * 16 + g + rh * 8;
                float v0 = acc[mt][nt][rh*2] + b0;
                float v1 = acc[mt][nt][rh*2+1] + b1;
                if (EPI == 0) {
                    *(float2*)(C + (size_t)m * N + n) = make_float2(v0, v1);
                } else {
                    int bi = m >> 11, mm = m & (M_ - 1);
                    int which = n >> 8, dd = n & 255;
                    int h = dd >> 5, c = dd & 31;
                    float* dst = (which == 0 ? g_q : which == 1 ? g_k : g_v)
                               + (size_t)(((bi << 3) + h) * M_ + mm) * DH_ + c;
                    *(float2*)dst = make_float2(v0, v1);
                }
            }
        }
    }
}

// ---------------- TN tf32 GEMM (split-K): S_partial = inc^T @ attnout ------
__global__ __launch_bounds__(256, 2)
void gemm_tn_S_tf32(const float* __restrict__ inc)
{
    __shared__ unsigned As[32][132];
    __shared__ unsigned Bs[32][132];
    const int t = threadIdx.x, lane = t & 31, w = t >> 5;
    const int z = blockIdx.z;
    const int b = z >> 2, sk = z & 3;
    const int e0 = blockIdx.y * 128, d0 = blockIdx.x * 128;
    const int kbase = sk * KCH;
    const int wm = (w & 1) * 64, wn = (w >> 1) * 32;
    const int g = lane >> 2, qt = lane & 3;
    const float* Ag = inc       + (size_t)b * M_ * E_;
    const float* Bg = g_attnout + (size_t)b * M_ * D_;

    float acc[4][4][4];
#pragma unroll
    for (int i = 0; i < 4; i++)
#pragma unroll
        for (int j = 0; j < 4; j++)
#pragma unroll
            for (int r = 0; r < 4; r++) acc[i][j][r] = 0.f;

    for (int k0 = 0; k0 < KCH; k0 += 32) {
#pragma unroll
        for (int p = 0; p < 4; p++) {
            int linear = p * 1024 + t * 4;
            int r = linear >> 7, c = linear & 127;
            int krow = kbase + k0 + r;
            float4 av = *(const float4*)(Ag + (size_t)krow * E_ + e0 + c);
            As[r][c] = f2tf(av.x); As[r][c+1] = f2tf(av.y);
            As[r][c+2] = f2tf(av.z); As[r][c+3] = f2tf(av.w);
            float4 bv = *(const float4*)(Bg + (size_t)krow * D_ + d0 + c);
            Bs[r][c] = f2tf(bv.x); Bs[r][c+1] = f2tf(bv.y);
            Bs[r][c+2] = f2tf(bv.z); Bs[r][c+3] = f2tf(bv.w);
        }
        __syncthreads();
#pragma unroll
        for (int ks = 0; ks < 4; ks++) {
            unsigned af[4][4], bf[4][2];
            const int kc = ks * 8 + qt;
#pragma unroll
            for (int mt = 0; mt < 4; mt++) {
                const int mr = wm + mt * 16 + g;
                af[mt][0] = As[kc][mr];     af[mt][1] = As[kc][mr+8];
                af[mt][2] = As[kc+4][mr];   af[mt][3] = As[kc+4][mr+8];
            }
#pragma unroll
            for (int nt = 0; nt < 4; nt++) {
                const int nr = wn + nt * 8 + g;
                bf[nt][0] = Bs[kc][nr];     bf[nt][1] = Bs[kc+4][nr];
            }
#pragma unroll
            for (int mt = 0; mt < 4; mt++)
#pragma unroll
                for (int nt = 0; nt < 4; nt++)
                    mma8(acc[mt][nt], af[mt], bf[nt]);
        }
        __syncthreads();
    }

    float* Cp = g_Spart + (size_t)(sk * B_ + b) * E_ * D_;
#pragma unroll
    for (int mt = 0; mt < 4; mt++)
#pragma unroll
        for (int nt = 0; nt < 4; nt++) {
            const int d = d0 + wn + nt * 8 + 2 * qt;
#pragma unroll
            for (int rh = 0; rh < 2; rh++) {
                const int e = e0 + wm + mt * 16 + g + rh * 8;
                *(float2*)(Cp + (size_t)e * D_ + d) =
                    make_float2(acc[mt][nt][rh*2], acc[mt][nt][rh*2+1]);
            }
        }
}

// deterministic split-K reduction
__global__ void reduce_S()
{
    const int i = blockIdx.x * 256 + threadIdx.x;
    const int N4 = B_*E_*D_/4;
    const float4* p = (const float4*)g_Spart;
    float4 a = p[i], b = p[i + N4], c = p[i + 2*N4], d = p[i + 3*N4];
    ((float4*)g_S)[i] = make_float4(a.x+b.x+c.x+d.x, a.y+b.y+c.y+d.y,
                                    a.z+b.z+c.z+d.z, a.w+b.w+c.w+d.w);
}

// ---------------- flash attention: tf32 QK, fp16 PV (FA2-style) ------------
// grid (16 q-tiles, 32 bh), block 128 (4 warps). Warp owns 32 q rows.
// P: S-acc fragments pack directly into fp16 A-operands (cvt.f16x2, no smem,
// no shuffles). V: fp16 row-major smem, B-frags via ldmatrix.x2.trans.
#define FTK 64
#define KV_STRIDE 36
#define VST16 40    // fp16 elems per V row (64B data + 16B pad, 16B-aligned rows)

__global__ __launch_bounds__(128, 3)
void flash_attn_tf32()
{
    __shared__ unsigned Ks[FTK*KV_STRIDE];
    __shared__ __align__(16) unsigned Vs16[FTK*VST16/2];   // fp16 pairs

    const int t = threadIdx.x, lane = t & 31, w = t >> 5;
    const int g = lane >> 2, qt = lane & 3;
    const int bh = blockIdx.y;
    const int qbase = blockIdx.x * 128 + w * 32;

    const float scale = 0.17677669529663687f;   // 1/sqrt(32)
    const float* qp = g_q + ((size_t)bh * M_ + qbase) * DH_;

    unsigned qf[2][4][4];
#pragma unroll
    for (int mt = 0; mt < 2; mt++)
#pragma unroll
        for (int ks = 0; ks < 4; ks++) {
            int r0 = mt * 16 + g, c0 = ks * 8 + qt;
            qf[mt][ks][0] = f2tf(scale * qp[r0*32 + c0]);
            qf[mt][ks][1] = f2tf(scale * qp[(r0+8)*32 + c0]);
            qf[mt][ks][2] = f2tf(scale * qp[r0*32 + c0 + 4]);
            qf[mt][ks][3] = f2tf(scale * qp[(r0+8)*32 + c0 + 4]);
        }

    float of[2][4][4];
#pragma unroll
    for (int i = 0; i < 2; i++)
#pragma unroll
        for (int j = 0; j < 4; j++)
#pragma unroll
            for (int r = 0; r < 4; r++) of[i][j][r] = 0.f;
    float mr[2][2] = {{-1e30f,-1e30f},{-1e30f,-1e30f}};
    float lr[2][2] = {{0.f,0.f},{0.f,0.f}};

    const float* kb = g_k + (size_t)bh * M_ * DH_;
    const float* vb = g_v + (size_t)bh * M_ * DH_;

    const unsigned vsbase = (unsigned)__cvta_generic_to_shared(Vs16);
    const int ldkr = (lane & 7) + 8 * ((lane >> 3) & 1);   // ldmatrix row-in-chunk

    for (int kt = 0; kt < M_; kt += FTK) {
        __syncthreads();
#pragma unroll
        for (int p = 0; p < 4; p++) {
            int linear = p * 512 + t * 4;
            int r = linear >> 5, c = linear & 31;
            float4 kv = *(const float4*)(kb + (size_t)(kt + r) * DH_ + c);
            Ks[r*KV_STRIDE + c]   = f2tf(kv.x); Ks[r*KV_STRIDE + c+1] = f2tf(kv.y);
            Ks[r*KV_STRIDE + c+2] = f2tf(kv.z); Ks[r*KV_STRIDE + c+3] = f2tf(kv.w);
            float4 vv = *(const float4*)(vb + (size_t)(kt + r) * DH_ + c);
            Vs16[r*(VST16/2) + c/2]     = pk16(vv.x, vv.y);
            Vs16[r*(VST16/2) + c/2 + 1] = pk16(vv.z, vv.w);
        }
        __syncthreads();

        // S = Q @ K^T  (per warp: 32q x 64keys, tf32)
        float sf[2][8][4];
#pragma unroll
        for (int i = 0; i < 2; i++)
#pragma unroll
            for (int j = 0; j < 8; j++)
#pragma unroll
                for (int r = 0; r < 4; r++) sf[i][j][r] = 0.f;
#pragma unroll
        for (int ks = 0; ks < 4; ks++) {
            unsigned bfk[8][2];
            const int kc = ks * 8 + qt;
#pragma unroll
            for (int n = 0; n < 8; n++) {
                bfk[n][0] = Ks[(n*8 + g)*KV_STRIDE + kc];
                bfk[n][1] = Ks[(n*8 + g)*KV_STRIDE + kc + 4];
            }
#pragma unroll
            for (int mt = 0; mt < 2; mt++)
#pragma unroll
                for (int n = 0; n < 8; n++)
                    mma8(sf[mt][n], qf[mt][ks], bfk[n]);
        }

        // online softmax on fragments; overwrite sf with exp values (f32)
#pragma unroll
        for (int mt = 0; mt < 2; mt++) {
#pragma unroll
            for (int rh = 0; rh < 2; rh++) {
                float mx = -1e30f;
#pragma unroll
                for (int n = 0; n < 8; n++) {
                    mx = fmaxf(mx, sf[mt][n][rh*2]);
                    mx = fmaxf(mx, sf[mt][n][rh*2+1]);
                }
                mx = fmaxf(mx, __shfl_xor_sync(~0u, mx, 1));
                mx = fmaxf(mx, __shfl_xor_sync(~0u, mx, 2));
                float mn = fmaxf(mr[mt][rh], mx);
                float corr = __expf(mr[mt][rh] - mn);
                mr[mt][rh] = mn;
                lr[mt][rh] *= corr;
#pragma unroll
                for (int nd = 0; nd < 4; nd++) {
                    of[mt][nd][rh*2]   *= corr;
                    of[mt][nd][rh*2+1] *= corr;
                }
                float ls = 0.f;
#pragma unroll
                for (int n = 0; n < 8; n++) {
                    float e0 = __expf(sf[mt][n][rh*2]   - mn);
                    float e1 = __expf(sf[mt][n][rh*2+1] - mn);
                    ls += e0 + e1;
                    sf[mt][n][rh*2] = e0; sf[mt][n][rh*2+1] = e1;
                }
                lr[mt][rh] += ls;
            }
        }

        // O += P @ V : fp16 m16n8k16. A-frags pack straight from S-acc;
        // B-frags via ldmatrix.trans from row-major fp16 V.
#pragma unroll
        for (int j = 0; j < 4; j++) {             // 16-key chunks
            unsigned bfv[4][2];
            const int kr = 16*j + ldkr;
#pragma unroll
            for (int nd = 0; nd < 4; nd++) {
                unsigned ad = vsbase + (unsigned)(kr * (VST16*2) + nd * 16);
                asm volatile(
                    "ldmatrix.sync.aligned.m8n8.x2.trans.shared.b16 {%0,%1},[%2];"
                    : "=r"(bfv[nd][0]), "=r"(bfv[nd][1]) : "r"(ad));
            }
#pragma unroll
            for (int mt = 0; mt < 2; mt++) {
                unsigned af[4];
                af[0] = pk16(sf[mt][2*j][0],   sf[mt][2*j][1]);
                af[1] = pk16(sf[mt][2*j][2],   sf[mt][2*j][3]);
                af[2] = pk16(sf[mt][2*j+1][0], sf[mt][2*j+1][1]);
                af[3] = pk16(sf[mt][2*j+1][2], sf[mt][2*j+1][3]);
#pragma unroll
                for (int nd = 0; nd < 4; nd++)
                    mma16(of[mt][nd], af, bfv[nd]);
            }
        }
    }

    // finalize + store into g_attn [b][m][h*32 + d]
    const int b = bh >> 3, h = bh & 7;
#pragma unroll
    for (int mt = 0; mt < 2; mt++)
#pragma unroll
        for (int rh = 0; rh < 2; rh++) {
            float l = lr[mt][rh];
            l += __shfl_xor_sync(~0u, l, 1);
            l += __shfl_xor_sync(~0u, l, 2);
            float inv = 1.f / l;
            const int q = qbase + mt*16 + g + rh*8;
            float* op = g_attn + ((size_t)b * M_ + q) * D_ + h * DH_;
#pragma unroll
            for (int nd = 0; nd < 4; nd++)
                *(float2*)(op + nd*8 + 2*qt) =
                    make_float2(of[mt][nd][rh*2]*inv, of[mt][nd][rh*2+1]*inv);
        }
}

// ---------------- softmax over hyperedge dim + ef = S*W --------------------
__global__ void softmax_e()
{
    const int t = threadIdx.x, lane = t & 31, wid = t >> 5;
    const int col = blockIdx.x * 8 + wid;
    const int b = col >> 8, d = col & 255;
    const float* base = g_S + (size_t)b * E_ * D_ + d;
    float v[32];
    float mx = -1e30f;
#pragma unroll
    for (int r = 0; r < 32; r++) {
        float x = base[(size_t)(lane + r*32) * D_];
        v[r] = x; mx = fmaxf(mx, x);
    }
#pragma unroll
    for (int off = 16; off; off >>= 1) mx = fmaxf(mx, __shfl_xor_sync(~0u, mx, off));
    float se = 0.f;
#pragma unroll
    for (int r = 0; r < 32; r++) se += __expf(v[r] - mx);
#pragma unroll
    for (int off = 16; off; off >>= 1) se += __shfl_xor_sync(~0u, se, off);
    float inv = 1.f / se;
    float* ob = g_ef + (size_t)b * E_ * D_ + d;
#pragma unroll
    for (int r = 0; r < 32; r++)
        ob[(size_t)(lane + r*32) * D_] = v[r] * __expf(v[r] - mx) * inv;
}

// ---------------- LayerNorm + residual -------------------------------------
__global__ void ln_residual(const float* __restrict__ prev,
                            const float* __restrict__ gamma,
                            const float* __restrict__ beta,
                            const float* __restrict__ alphap,
                            float* __restrict__ out)
{
    const int t = threadIdx.x, lane = t & 31, wid = t >> 5;
    const int row = blockIdx.x * 8 + wid;
    const float* x = g_ef2 + (size_t)row * D_;
    float xs[8], sum = 0.f, sq = 0.f;
#pragma unroll
    for (int c = 0; c < 8; c++) {
        float v = x[lane + c*32];
        xs[c] = v; sum += v; sq += v*v;
    }
#pragma unroll
    for (int off = 16; off; off >>= 1) {
        sum += __shfl_xor_sync(~0u, sum, off);
        sq  += __shfl_xor_sync(~0u, sq,  off);
    }
    const float mu   = sum * (1.f / D_);
    const float var  = sq * (1.f / D_) - mu * mu;
    const float rstd = rsqrtf(var + 1e-5f);
    const float alpha = *alphap;
#pragma unroll
    for (int c = 0; c < 8; c++) {
        int d = lane + c*32;
        float y = (xs[c] - mu) * rstd * gamma[d] + beta[d];
        size_t idx = (size_t)row * D_ + d;
        out[idx] = (1.f + alpha) * prev[idx] + (1.f - alpha) * y;
    }
}

// ---------------- launch ----------------------------------------------------
extern "C" void kernel_launch(void* const* d_in, const int* in_sizes, int n_in,
                              void* d_out, int out_size)
{
    const float* feature = (const float*)d_in[0];
    const float* inc     = (const float*)d_in[1];
    const float* prev    = (const float*)d_in[2];
    const float* inw     = (const float*)d_in[3];
    const float* inb     = (const float*)d_in[4];
    const float* outw    = (const float*)d_in[5];
    const float* outb    = (const float*)d_in[6];
    const float* projw   = (const float*)d_in[7];
    const float* gamma   = (const float*)d_in[8];
    const float* beta    = (const float*)d_in[9];
    const float* alphap  = (const float*)d_in[10];
    float* out = (float*)d_out;

    float *p_attn = 0, *p_attnout = 0, *p_ef = 0, *p_ef2 = 0;
    cudaGetSymbolAddress((void**)&p_attn,    g_attn);
    cudaGetSymbolAddress((void**)&p_attnout, g_attnout);
    cudaGetSymbolAddress((void**)&p_ef,      g_ef);
    cudaGetSymbolAddress((void**)&p_ef2,     g_ef2);

    // 1. QKV projection -> scatter to q/k/v
    gemm_nt_tf32<1><<<dim3(6, 64), 256>>>(feature, inw, inb, (float*)0, B_*M_, 3*D_, D_);
    // 2. attention (tf32 QK, fp16 PV)
    flash_attn_tf32<<<dim3(16, 32), 128>>>();
    // 3. out_proj
    gemm_nt_tf32<0><<<dim3(2, 64), 256>>>(p_attn, outw, outb, p_attnout, B_*M_, D_, D_);
    // 4. S = inc^T @ attnout (split-K partials) + reduce
    gemm_tn_S_tf32<<<dim3(2, 8, B_*SPLITK), 256>>>(inc);
    reduce_S<<<B_*E_*D_/4/256, 256>>>();
    // 5. softmax over e + ef = S*W
    softmax_e<<<128, 256>>>();
    // 6. final projection
    gemm_nt_tf32<0><<<dim3(2, 32), 256>>>(p_ef, projw, (float*)0, p_ef2, B_*E_, D_, D_);
    // 7. LN + residual mix
    ln_residual<<<512, 256>>>(prev, gamma, beta, alphap, out);
}

// round 13
// speedup vs baseline: 1.7828x; 1.1300x over previous
#include <cuda_runtime.h>
#include <math.h>

#define B_ 4
#define M_ 2048
#define E_ 1024
#define D_ 256
#define H_ 8
#define DH_ 32
#define SPLITK 4
#define KCH (M_ / SPLITK)   // 512

// ---------------- scratch (device globals: allocation-free) ----------------
__device__ float g_q[B_*H_*M_*DH_];
__device__ float g_k[B_*H_*M_*DH_];
__device__ float g_v[B_*H_*M_*DH_];
__device__ float g_attn[B_*M_*D_];
__device__ float g_attnout[B_*M_*D_];
__device__ float g_Spart[SPLITK*B_*E_*D_];
__device__ float g_S[B_*E_*D_];
__device__ float g_ef[B_*E_*D_];
__device__ float g_ef2[B_*E_*D_];

// ---------------- helpers ---------------------------------------------------
__device__ __forceinline__ unsigned f2tf(float f) {
    unsigned u;
    asm("cvt.rna.tf32.f32 %0, %1;" : "=r"(u) : "f"(f));
    return u;
}
// D += A@B, m16n8k8 tf32
__device__ __forceinline__ void mma8(float* d, const unsigned* a, const unsigned* b) {
    asm volatile(
        "mma.sync.aligned.m16n8k8.row.col.f32.tf32.tf32.f32 "
        "{%0,%1,%2,%3},{%4,%5,%6,%7},{%8,%9},{%0,%1,%2,%3};"
        : "+f"(d[0]), "+f"(d[1]), "+f"(d[2]), "+f"(d[3])
        : "r"(a[0]), "r"(a[1]), "r"(a[2]), "r"(a[3]), "r"(b[0]), "r"(b[1]));
}
// D += A@B, m16n8k16 fp16 in, fp32 accum
__device__ __forceinline__ void mma16(float* d, const unsigned* a, const unsigned* b) {
    asm volatile(
        "mma.sync.aligned.m16n8k16.row.col.f32.f16.f16.f32 "
        "{%0,%1,%2,%3},{%4,%5,%6,%7},{%8,%9},{%0,%1,%2,%3};"
        : "+f"(d[0]), "+f"(d[1]), "+f"(d[2]), "+f"(d[3])
        : "r"(a[0]), "r"(a[1]), "r"(a[2]), "r"(a[3]), "r"(b[0]), "r"(b[1]));
}
// pack two f32 -> f16x2 (lo = first elem)
__device__ __forceinline__ unsigned pk16(float lo, float hi) {
    unsigned r;
    asm("cvt.rn.f16x2.f32 %0, %1, %2;" : "=r"(r) : "f"(hi), "f"(lo));
    return r;
}

// ---------------- NT fp16 GEMM: C[M,N] = A[M,K] @ Bw[N,K]^T (+bias) --------
// 128x128x32 tile, 256 thr, warp tile 64x32. fp16 operands, fp32 accum.
// smem rows: 40 halves = 20 words; fragment reads hit banks 20g mod 32
// (perfect 8-way spread) -> conflict-free.
#define NTSTR 20
template<int EPI>
__global__ __launch_bounds__(256, 2)
void gemm_nt_f16(const float* __restrict__ A, const float* __restrict__ Bw,
                 const float* __restrict__ bias, float* __restrict__ C,
                 int M, int N, int K)
{
    __shared__ unsigned As[128*NTSTR];
    __shared__ unsigned Bs[128*NTSTR];
    const int t = threadIdx.x, lane = t & 31, w = t >> 5;
    const int m0 = blockIdx.y * 128, n0 = blockIdx.x * 128;
    const int wm = (w & 1) * 64, wn = (w >> 1) * 32;
    const int g = lane >> 2, qt = lane & 3;

    float acc[4][4][4];
#pragma unroll
    for (int i = 0; i < 4; i++)
#pragma unroll
        for (int j = 0; j < 4; j++)
#pragma unroll
            for (int r = 0; r < 4; r++) acc[i][j][r] = 0.f;

    for (int k0 = 0; k0 < K; k0 += 32) {
#pragma unroll
        for (int p = 0; p < 4; p++) {
            int lin = p * 1024 + t * 4;
            int r = lin >> 5, c = lin & 31;
            float4 av = *(const float4*)(A + (size_t)(m0 + r) * K + k0 + c);
            As[r*NTSTR + c/2]     = pk16(av.x, av.y);
            As[r*NTSTR + c/2 + 1] = pk16(av.z, av.w);
            float4 bv = *(const float4*)(Bw + (size_t)(n0 + r) * K + k0 + c);
            Bs[r*NTSTR + c/2]     = pk16(bv.x, bv.y);
            Bs[r*NTSTR + c/2 + 1] = pk16(bv.z, bv.w);
        }
        __syncthreads();
#pragma unroll
        for (int ks = 0; ks < 2; ks++) {          // two k16 steps
            const int kw = ks * 8 + qt;           // word offset of pair 2qt
            unsigned af[4][4], bf[4][2];
#pragma unroll
            for (int mt = 0; mt < 4; mt++) {
                const int mr = wm + mt * 16 + g;
                af[mt][0] = As[mr*NTSTR + kw];
                af[mt][1] = As[(mr+8)*NTSTR + kw];
                af[mt][2] = As[mr*NTSTR + kw + 4];
                af[mt][3] = As[(mr+8)*NTSTR + kw + 4];
            }
#pragma unroll
            for (int nt = 0; nt < 4; nt++) {
                const int nr = wn + nt * 8 + g;
                bf[nt][0] = Bs[nr*NTSTR + kw];
                bf[nt][1] = Bs[nr*NTSTR + kw + 4];
            }
#pragma unroll
            for (int mt = 0; mt < 4; mt++)
#pragma unroll
                for (int nt = 0; nt < 4; nt++)
                    mma16(acc[mt][nt], af[mt], bf[nt]);
        }
        __syncthreads();
    }

#pragma unroll
    for (int mt = 0; mt < 4; mt++) {
#pragma unroll
        for (int nt = 0; nt < 4; nt++) {
            const int n = n0 + wn + nt * 8 + 2 * qt;
            float b0 = bias ? bias[n] : 0.f;
            float b1 = bias ? bias[n+1] : 0.f;
#pragma unroll
            for (int rh = 0; rh < 2; rh++) {
                const int m = m0 + wm + mt * 16 + g + rh * 8;
                float v0 = acc[mt][nt][rh*2] + b0;
                float v1 = acc[mt][nt][rh*2+1] + b1;
                if (EPI == 0) {
                    *(float2*)(C + (size_t)m * N + n) = make_float2(v0, v1);
                } else {
                    int bi = m >> 11, mm = m & (M_ - 1);
                    int which = n >> 8, dd = n & 255;
                    int h = dd >> 5, c = dd & 31;
                    float* dst = (which == 0 ? g_q : which == 1 ? g_k : g_v)
                               + (size_t)(((bi << 3) + h) * M_ + mm) * DH_ + c;
                    *(float2*)dst = make_float2(v0, v1);
                }
            }
        }
    }
}

// ---------------- TN fp16 GEMM (split-K): S_partial = inc^T @ attnout ------
// A/B stay in native [token][col] layout; transposed fragments come from
// ldmatrix .trans. Row stride 136 halves = 272B (16B-aligned, word stride
// 68 == 4 mod 32 -> conflict-free trans reads).
#define TNSTR 68     // words per row (136 halves)
__global__ __launch_bounds__(256, 2)
void gemm_tn_S_f16(const float* __restrict__ inc)
{
    __shared__ unsigned As[32*TNSTR];   // [token][e] fp16 pairs
    __shared__ unsigned Bs[32*TNSTR];   // [token][d] fp16 pairs
    const int t = threadIdx.x, lane = t & 31, w = t >> 5;
    const int z = blockIdx.z;
    const int b = z >> 2, sk = z & 3;
    const int e0 = blockIdx.y * 128, d0 = blockIdx.x * 128;
    const int kbase = sk * KCH;
    const int wm = (w & 1) * 64, wn = (w >> 1) * 32;
    const int g = lane >> 2, qt = lane & 3;
    const float* Ag = inc       + (size_t)b * M_ * E_;
    const float* Bg = g_attnout + (size_t)b * M_ * D_;

    const unsigned abase = (unsigned)__cvta_generic_to_shared(As);
    const unsigned bbase = (unsigned)__cvta_generic_to_shared(Bs);
    const int il = lane & 7, qq = lane >> 3;        // x4 quadrant decode
    const int q2 = (lane >> 3) & 1;                 // x2 half decode

    float acc[4][4][4];
#pragma unroll
    for (int i = 0; i < 4; i++)
#pragma unroll
        for (int j = 0; j < 4; j++)
#pragma unroll
            for (int r = 0; r < 4; r++) acc[i][j][r] = 0.f;

    for (int k0 = 0; k0 < KCH; k0 += 32) {
#pragma unroll
        for (int p = 0; p < 4; p++) {
            int lin = p * 1024 + t * 4;
            int r = lin >> 7, c = lin & 127;
            int krow = kbase + k0 + r;
            float4 av = *(const float4*)(Ag + (size_t)krow * E_ + e0 + c);
            As[r*TNSTR + c/2]     = pk16(av.x, av.y);
            As[r*TNSTR + c/2 + 1] = pk16(av.z, av.w);
            float4 bv = *(const float4*)(Bg + (size_t)krow * D_ + d0 + c);
            Bs[r*TNSTR + c/2]     = pk16(bv.x, bv.y);
            Bs[r*TNSTR + c/2 + 1] = pk16(bv.z, bv.w);
        }
        __syncthreads();
#pragma unroll
        for (int ks = 0; ks < 2; ks++) {          // two k16 steps
            const int kc0 = ks * 16;
            unsigned af[4][4], bf[4][2];
#pragma unroll
            for (int mt = 0; mt < 4; mt++) {
                const int ecol = wm + mt * 16 + (qq & 1) * 8;  // halves
                unsigned ad = abase
                    + (unsigned)((kc0 + (qq >> 1) * 8 + il) * (TNSTR*4) + ecol * 2);
                asm volatile(
                    "ldmatrix.sync.aligned.m8n8.x4.trans.shared.b16 "
                    "{%0,%1,%2,%3},[%4];"
                    : "=r"(af[mt][0]), "=r"(af[mt][1]),
                      "=r"(af[mt][2]), "=r"(af[mt][3]) : "r"(ad));
            }
#pragma unroll
            for (int nt = 0; nt < 4; nt++) {
                const int ncol = wn + nt * 8;                  // halves
                unsigned ad = bbase
                    + (unsigned)((kc0 + q2 * 8 + il) * (TNSTR*4) + ncol * 2);
                asm volatile(
                    "ldmatrix.sync.aligned.m8n8.x2.trans.shared.b16 "
                    "{%0,%1},[%2];"
                    : "=r"(bf[nt][0]), "=r"(bf[nt][1]) : "r"(ad));
            }
#pragma unroll
            for (int mt = 0; mt < 4; mt++)
#pragma unroll
                for (int nt = 0; nt < 4; nt++)
                    mma16(acc[mt][nt], af[mt], bf[nt]);
        }
        __syncthreads();
    }

    float* Cp = g_Spart + (size_t)(sk * B_ + b) * E_ * D_;
#pragma unroll
    for (int mt = 0; mt < 4; mt++)
#pragma unroll
        for (int nt = 0; nt < 4; nt++) {
            const int d = d0 + wn + nt * 8 + 2 * qt;
#pragma unroll
            for (int rh = 0; rh < 2; rh++) {
                const int e = e0 + wm + mt * 16 + g + rh * 8;
                *(float2*)(Cp + (size_t)e * D_ + d) =
                    make_float2(acc[mt][nt][rh*2], acc[mt][nt][rh*2+1]);
            }
        }
}

// deterministic split-K reduction
__global__ void reduce_S()
{
    const int i = blockIdx.x * 256 + threadIdx.x;
    const int N4 = B_*E_*D_/4;
    const float4* p = (const float4*)g_Spart;
    float4 a = p[i], b = p[i + N4], c = p[i + 2*N4], d = p[i + 3*N4];
    ((float4*)g_S)[i] = make_float4(a.x+b.x+c.x+d.x, a.y+b.y+c.y+d.y,
                                    a.z+b.z+c.z+d.z, a.w+b.w+c.w+d.w);
}

// ---------------- flash attention: tf32 QK, fp16 PV (unchanged from R12) ---
#define FTK 64
#define KV_STRIDE 36
#define VST16 40

__global__ __launch_bounds__(128, 3)
void flash_attn_tf32()
{
    __shared__ unsigned Ks[FTK*KV_STRIDE];
    __shared__ __align__(16) unsigned Vs16[FTK*VST16/2];

    const int t = threadIdx.x, lane = t & 31, w = t >> 5;
    const int g = lane >> 2, qt = lane & 3;
    const int bh = blockIdx.y;
    const int qbase = blockIdx.x * 128 + w * 32;

    const float scale = 0.17677669529663687f;
    const float* qp = g_q + ((size_t)bh * M_ + qbase) * DH_;

    unsigned qf[2][4][4];
#pragma unroll
    for (int mt = 0; mt < 2; mt++)
#pragma unroll
        for (int ks = 0; ks < 4; ks++) {
            int r0 = mt * 16 + g, c0 = ks * 8 + qt;
            qf[mt][ks][0] = f2tf(scale * qp[r0*32 + c0]);
            qf[mt][ks][1] = f2tf(scale * qp[(r0+8)*32 + c0]);
            qf[mt][ks][2] = f2tf(scale * qp[r0*32 + c0 + 4]);
            qf[mt][ks][3] = f2tf(scale * qp[(r0+8)*32 + c0 + 4]);
        }

    float of[2][4][4];
#pragma unroll
    for (int i = 0; i < 2; i++)
#pragma unroll
        for (int j = 0; j < 4; j++)
#pragma unroll
            for (int r = 0; r < 4; r++) of[i][j][r] = 0.f;
    float mr[2][2] = {{-1e30f,-1e30f},{-1e30f,-1e30f}};
    float lr[2][2] = {{0.f,0.f},{0.f,0.f}};

    const float* kb = g_k + (size_t)bh * M_ * DH_;
    const float* vb = g_v + (size_t)bh * M_ * DH_;

    const unsigned vsbase = (unsigned)__cvta_generic_to_shared(Vs16);
    const int ldkr = (lane & 7) + 8 * ((lane >> 3) & 1);

    for (int kt = 0; kt < M_; kt += FTK) {
        __syncthreads();
#pragma unroll
        for (int p = 0; p < 4; p++) {
            int linear = p * 512 + t * 4;
            int r = linear >> 5, c = linear & 31;
            float4 kv = *(const float4*)(kb + (size_t)(kt + r) * DH_ + c);
            Ks[r*KV_STRIDE + c]   = f2tf(kv.x); Ks[r*KV_STRIDE + c+1] = f2tf(kv.y);
            Ks[r*KV_STRIDE + c+2] = f2tf(kv.z); Ks[r*KV_STRIDE + c+3] = f2tf(kv.w);
            float4 vv = *(const float4*)(vb + (size_t)(kt + r) * DH_ + c);
            Vs16[r*(VST16/2) + c/2]     = pk16(vv.x, vv.y);
            Vs16[r*(VST16/2) + c/2 + 1] = pk16(vv.z, vv.w);
        }
        __syncthreads();

        float sf[2][8][4];
#pragma unroll
        for (int i = 0; i < 2; i++)
#pragma unroll
            for (int j = 0; j < 8; j++)
#pragma unroll
                for (int r = 0; r < 4; r++) sf[i][j][r] = 0.f;
#pragma unroll
        for (int ks = 0; ks < 4; ks++) {
            unsigned bfk[8][2];
            const int kc = ks * 8 + qt;
#pragma unroll
            for (int n = 0; n < 8; n++) {
                bfk[n][0] = Ks[(n*8 + g)*KV_STRIDE + kc];
                bfk[n][1] = Ks[(n*8 + g)*KV_STRIDE + kc + 4];
            }
#pragma unroll
            for (int mt = 0; mt < 2; mt++)
#pragma unroll
                for (int n = 0; n < 8; n++)
                    mma8(sf[mt][n], qf[mt][ks], bfk[n]);
        }

#pragma unroll
        for (int mt = 0; mt < 2; mt++) {
#pragma unroll
            for (int rh = 0; rh < 2; rh++) {
                float mx = -1e30f;
#pragma unroll
                for (int n = 0; n < 8; n++) {
                    mx = fmaxf(mx, sf[mt][n][rh*2]);
                    mx = fmaxf(mx, sf[mt][n][rh*2+1]);
                }
                mx = fmaxf(mx, __shfl_xor_sync(~0u, mx, 1));
                mx = fmaxf(mx, __shfl_xor_sync(~0u, mx, 2));
                float mn = fmaxf(mr[mt][rh], mx);
                float corr = __expf(mr[mt][rh] - mn);
                mr[mt][rh] = mn;
                lr[mt][rh] *= corr;
#pragma unroll
                for (int nd = 0; nd < 4; nd++) {
                    of[mt][nd][rh*2]   *= corr;
                    of[mt][nd][rh*2+1] *= corr;
                }
                float ls = 0.f;
#pragma unroll
                for (int n = 0; n < 8; n++) {
                    float e0 = __expf(sf[mt][n][rh*2]   - mn);
                    float e1 = __expf(sf[mt][n][rh*2+1] - mn);
                    ls += e0 + e1;
                    sf[mt][n][rh*2] = e0; sf[mt][n][rh*2+1] = e1;
                }
                lr[mt][rh] += ls;
            }
        }

#pragma unroll
        for (int j = 0; j < 4; j++) {
            unsigned bfv[4][2];
            const int kr = 16*j + ldkr;
#pragma unroll
            for (int nd = 0; nd < 4; nd++) {
                unsigned ad = vsbase + (unsigned)(kr * (VST16*2) + nd * 16);
                asm volatile(
                    "ldmatrix.sync.aligned.m8n8.x2.trans.shared.b16 {%0,%1},[%2];"
                    : "=r"(bfv[nd][0]), "=r"(bfv[nd][1]) : "r"(ad));
            }
#pragma unroll
            for (int mt = 0; mt < 2; mt++) {
                unsigned af[4];
                af[0] = pk16(sf[mt][2*j][0],   sf[mt][2*j][1]);
                af[1] = pk16(sf[mt][2*j][2],   sf[mt][2*j][3]);
                af[2] = pk16(sf[mt][2*j+1][0], sf[mt][2*j+1][1]);
                af[3] = pk16(sf[mt][2*j+1][2], sf[mt][2*j+1][3]);
#pragma unroll
                for (int nd = 0; nd < 4; nd++)
                    mma16(of[mt][nd], af, bfv[nd]);
            }
        }
    }

    const int b = bh >> 3, h = bh & 7;
#pragma unroll
    for (int mt = 0; mt < 2; mt++)
#pragma unroll
        for (int rh = 0; rh < 2; rh++) {
            float l = lr[mt][rh];
            l += __shfl_xor_sync(~0u, l, 1);
            l += __shfl_xor_sync(~0u, l, 2);
            float inv = 1.f / l;
            const int q = qbase + mt*16 + g + rh*8;
            float* op = g_attn + ((size_t)b * M_ + q) * D_ + h * DH_;
#pragma unroll
            for (int nd = 0; nd < 4; nd++)
                *(float2*)(op + nd*8 + 2*qt) =
                    make_float2(of[mt][nd][rh*2]*inv, of[mt][nd][rh*2+1]*inv);
        }
}

// ---------------- softmax over hyperedge dim + ef = S*W --------------------
__global__ void softmax_e()
{
    const int t = threadIdx.x, lane = t & 31, wid = t >> 5;
    const int col = blockIdx.x * 8 + wid;
    const int b = col >> 8, d = col & 255;
    const float* base = g_S + (size_t)b * E_ * D_ + d;
    float v[32];
    float mx = -1e30f;
#pragma unroll
    for (int r = 0; r < 32; r++) {
        float x = base[(size_t)(lane + r*32) * D_];
        v[r] = x; mx = fmaxf(mx, x);
    }
#pragma unroll
    for (int off = 16; off; off >>= 1) mx = fmaxf(mx, __shfl_xor_sync(~0u, mx, off));
    float se = 0.f;
#pragma unroll
    for (int r = 0; r < 32; r++) se += __expf(v[r] - mx);
#pragma unroll
    for (int off = 16; off; off >>= 1) se += __shfl_xor_sync(~0u, se, off);
    float inv = 1.f / se;
    float* ob = g_ef + (size_t)b * E_ * D_ + d;
#pragma unroll
    for (int r = 0; r < 32; r++)
        ob[(size_t)(lane + r*32) * D_] = v[r] * __expf(v[r] - mx) * inv;
}

// ---------------- LayerNorm + residual -------------------------------------
__global__ void ln_residual(const float* __restrict__ prev,
                            const float* __restrict__ gamma,
                            const float* __restrict__ beta,
                            const float* __restrict__ alphap,
                            float* __restrict__ out)
{
    const int t = threadIdx.x, lane = t & 31, wid = t >> 5;
    const int row = blockIdx.x * 8 + wid;
    const float* x = g_ef2 + (size_t)row * D_;
    float xs[8], sum = 0.f, sq = 0.f;
#pragma unroll
    for (int c = 0; c < 8; c++) {
        float v = x[lane + c*32];
        xs[c] = v; sum += v; sq += v*v;
    }
#pragma unroll
    for (int off = 16; off; off >>= 1) {
        sum += __shfl_xor_sync(~0u, sum, off);
        sq  += __shfl_xor_sync(~0u, sq,  off);
    }
    const float mu   = sum * (1.f / D_);
    const float var  = sq * (1.f / D_) - mu * mu;
    const float rstd = rsqrtf(var + 1e-5f);
    const float alpha = *alphap;
#pragma unroll
    for (int c = 0; c < 8; c++) {
        int d = lane + c*32;
        float y = (xs[c] - mu) * rstd * gamma[d] + beta[d];
        size_t idx = (size_t)row * D_ + d;
        out[idx] = (1.f + alpha) * prev[idx] + (1.f - alpha) * y;
    }
}

// ---------------- launch ----------------------------------------------------
extern "C" void kernel_launch(void* const* d_in, const int* in_sizes, int n_in,
                              void* d_out, int out_size)
{
    const float* feature = (const float*)d_in[0];
    const float* inc     = (const float*)d_in[1];
    const float* prev    = (const float*)d_in[2];
    const float* inw     = (const float*)d_in[3];
    const float* inb     = (const float*)d_in[4];
    const float* outw    = (const float*)d_in[5];
    const float* outb    = (const float*)d_in[6];
    const float* projw   = (const float*)d_in[7];
    const float* gamma   = (const float*)d_in[8];
    const float* beta    = (const float*)d_in[9];
    const float* alphap  = (const float*)d_in[10];
    float* out = (float*)d_out;

    float *p_attn = 0, *p_attnout = 0, *p_ef = 0, *p_ef2 = 0;
    cudaGetSymbolAddress((void**)&p_attn,    g_attn);
    cudaGetSymbolAddress((void**)&p_attnout, g_attnout);
    cudaGetSymbolAddress((void**)&p_ef,      g_ef);
    cudaGetSymbolAddress((void**)&p_ef2,     g_ef2);

    // 1. QKV projection -> scatter to q/k/v
    gemm_nt_f16<1><<<dim3(6, 64), 256>>>(feature, inw, inb, (float*)0, B_*M_, 3*D_, D_);
    // 2. attention (tf32 QK, fp16 PV)
    flash_attn_tf32<<<dim3(16, 32), 128>>>();
    // 3. out_proj
    gemm_nt_f16<0><<<dim3(2, 64), 256>>>(p_attn, outw, outb, p_attnout, B_*M_, D_, D_);
    // 4. S = inc^T @ attnout (split-K partials) + reduce
    gemm_tn_S_f16<<<dim3(2, 8, B_*SPLITK), 256>>>(inc);
    reduce_S<<<B_*E_*D_/4/256, 256>>>();
    // 5. softmax over e + ef = S*W
    softmax_e<<<128, 256>>>();
    // 6. final projection
    gemm_nt_f16<0><<<dim3(2, 32), 256>>>(p_ef, projw, (float*)0, p_ef2, B_*E_, D_, D_);
    // 7. LN + residual mix
    ln_residual<<<512, 256>>>(prev, gamma, beta, alphap, out);
}

// round 15
// speedup vs baseline: 2.0674x; 1.1597x over previous
#include <cuda_runtime.h>
#include <math.h>

#define B_ 4
#define M_ 2048
#define E_ 1024
#define D_ 256
#define H_ 8
#define DH_ 32
#define SPLITK 4
#define KCH (M_ / SPLITK)   // 512

// ---------------- scratch (device globals: allocation-free) ----------------
__device__ float g_q[B_*H_*M_*DH_];
__device__ float g_k[B_*H_*M_*DH_];
__device__ float g_v[B_*H_*M_*DH_];
__device__ float g_attn[B_*M_*D_];
__device__ float g_attnout[B_*M_*D_];
__device__ float g_Spart[SPLITK*B_*E_*D_];
__device__ float g_S[B_*E_*D_];
__device__ float g_ef[B_*E_*D_];
__device__ float g_ef2[B_*E_*D_];

// ---------------- helpers ---------------------------------------------------
// D += A@B, m16n8k16 fp16 in, fp32 accum
__device__ __forceinline__ void mma16(float* d, const unsigned* a, const unsigned* b) {
    asm volatile(
        "mma.sync.aligned.m16n8k16.row.col.f32.f16.f16.f32 "
        "{%0,%1,%2,%3},{%4,%5,%6,%7},{%8,%9},{%0,%1,%2,%3};"
        : "+f"(d[0]), "+f"(d[1]), "+f"(d[2]), "+f"(d[3])
        : "r"(a[0]), "r"(a[1]), "r"(a[2]), "r"(a[3]), "r"(b[0]), "r"(b[1]));
}
// pack two f32 -> f16x2 (lo = first elem)
__device__ __forceinline__ unsigned pk16(float lo, float hi) {
    unsigned r;
    asm("cvt.rn.f16x2.f32 %0, %1, %2;" : "=r"(r) : "f"(hi), "f"(lo));
    return r;
}

// ---------------- NT fp16 GEMM: C[M,N] = A[M,K] @ Bw[N,K]^T (+bias) --------
#define NTSTR 20
template<int EPI>
__global__ __launch_bounds__(256, 2)
void gemm_nt_f16(const float* __restrict__ A, const float* __restrict__ Bw,
                 const float* __restrict__ bias, float* __restrict__ C,
                 int M, int N, int K)
{
    __shared__ unsigned As[128*NTSTR];
    __shared__ unsigned Bs[128*NTSTR];
    const int t = threadIdx.x, lane = t & 31, w = t >> 5;
    const int m0 = blockIdx.y * 128, n0 = blockIdx.x * 128;
    const int wm = (w & 1) * 64, wn = (w >> 1) * 32;
    const int g = lane >> 2, qt = lane & 3;

    float acc[4][4][4];
#pragma unroll
    for (int i = 0; i < 4; i++)
#pragma unroll
        for (int j = 0; j < 4; j++)
#pragma unroll
            for (int r = 0; r < 4; r++) acc[i][j][r] = 0.f;

    for (int k0 = 0; k0 < K; k0 += 32) {
#pragma unroll
        for (int p = 0; p < 4; p++) {
            int lin = p * 1024 + t * 4;
            int r = lin >> 5, c = lin & 31;
            float4 av = *(const float4*)(A + (size_t)(m0 + r) * K + k0 + c);
            As[r*NTSTR + c/2]     = pk16(av.x, av.y);
            As[r*NTSTR + c/2 + 1] = pk16(av.z, av.w);
            float4 bv = *(const float4*)(Bw + (size_t)(n0 + r) * K + k0 + c);
            Bs[r*NTSTR + c/2]     = pk16(bv.x, bv.y);
            Bs[r*NTSTR + c/2 + 1] = pk16(bv.z, bv.w);
        }
        __syncthreads();
#pragma unroll
        for (int ks = 0; ks < 2; ks++) {
            const int kw = ks * 8 + qt;
            unsigned af[4][4], bf[4][2];
#pragma unroll
            for (int mt = 0; mt < 4; mt++) {
                const int mr = wm + mt * 16 + g;
                af[mt][0] = As[mr*NTSTR + kw];
                af[mt][1] = As[(mr+8)*NTSTR + kw];
                af[mt][2] = As[mr*NTSTR + kw + 4];
                af[mt][3] = As[(mr+8)*NTSTR + kw + 4];
            }
#pragma unroll
            for (int nt = 0; nt < 4; nt++) {
                const int nr = wn + nt * 8 + g;
                bf[nt][0] = Bs[nr*NTSTR + kw];
                bf[nt][1] = Bs[nr*NTSTR + kw + 4];
            }
#pragma unroll
            for (int mt = 0; mt < 4; mt++)
#pragma unroll
                for (int nt = 0; nt < 4; nt++)
                    mma16(acc[mt][nt], af[mt], bf[nt]);
        }
        __syncthreads();
    }

#pragma unroll
    for (int mt = 0; mt < 4; mt++) {
#pragma unroll
        for (int nt = 0; nt < 4; nt++) {
            const int n = n0 + wn + nt * 8 + 2 * qt;
            float b0 = bias ? bias[n] : 0.f;
            float b1 = bias ? bias[n+1] : 0.f;
#pragma unroll
            for (int rh = 0; rh < 2; rh++) {
                const int m = m0 + wm + mt * 16 + g + rh * 8;
                float v0 = acc[mt][nt][rh*2] + b0;
                float v1 = acc[mt][nt][rh*2+1] + b1;
                if (EPI == 0) {
                    *(float2*)(C + (size_t)m * N + n) = make_float2(v0, v1);
                } else {
                    int bi = m >> 11, mm = m & (M_ - 1);
                    int which = n >> 8, dd = n & 255;
                    int h = dd >> 5, c = dd & 31;
                    float* dst = (which == 0 ? g_q : which == 1 ? g_k : g_v)
                               + (size_t)(((bi << 3) + h) * M_ + mm) * DH_ + c;
                    *(float2*)dst = make_float2(v0, v1);
                }
            }
        }
    }
}

// ---------------- TN fp16 GEMM (split-K): S_partial = inc^T @ attnout ------
#define TNSTR 68
__global__ __launch_bounds__(256, 2)
void gemm_tn_S_f16(const float* __restrict__ inc)
{
    __shared__ unsigned As[32*TNSTR];
    __shared__ unsigned Bs[32*TNSTR];
    const int t = threadIdx.x, lane = t & 31, w = t >> 5;
    const int z = blockIdx.z;
    const int b = z >> 2, sk = z & 3;
    const int e0 = blockIdx.y * 128, d0 = blockIdx.x * 128;
    const int kbase = sk * KCH;
    const int wm = (w & 1) * 64, wn = (w >> 1) * 32;
    const int g = lane >> 2, qt = lane & 3;
    const float* Ag = inc       + (size_t)b * M_ * E_;
    const float* Bg = g_attnout + (size_t)b * M_ * D_;

    const unsigned abase = (unsigned)__cvta_generic_to_shared(As);
    const unsigned bbase = (unsigned)__cvta_generic_to_shared(Bs);
    const int il = lane & 7, qq = lane >> 3;
    const int q2 = (lane >> 3) & 1;

    float acc[4][4][4];
#pragma unroll
    for (int i = 0; i < 4; i++)
#pragma unroll
        for (int j = 0; j < 4; j++)
#pragma unroll
            for (int r = 0; r < 4; r++) acc[i][j][r] = 0.f;

    for (int k0 = 0; k0 < KCH; k0 += 32) {
#pragma unroll
        for (int p = 0; p < 4; p++) {
            int lin = p * 1024 + t * 4;
            int r = lin >> 7, c = lin & 127;
            int krow = kbase + k0 + r;
            float4 av = *(const float4*)(Ag + (size_t)krow * E_ + e0 + c);
            As[r*TNSTR + c/2]     = pk16(av.x, av.y);
            As[r*TNSTR + c/2 + 1] = pk16(av.z, av.w);
            float4 bv = *(const float4*)(Bg + (size_t)krow * D_ + d0 + c);
            Bs[r*TNSTR + c/2]     = pk16(bv.x, bv.y);
            Bs[r*TNSTR + c/2 + 1] = pk16(bv.z, bv.w);
        }
        __syncthreads();
#pragma unroll
        for (int ks = 0; ks < 2; ks++) {
            const int kc0 = ks * 16;
            unsigned af[4][4], bf[4][2];
#pragma unroll
            for (int mt = 0; mt < 4; mt++) {
                const int ecol = wm + mt * 16 + (qq & 1) * 8;
                unsigned ad = abase
                    + (unsigned)((kc0 + (qq >> 1) * 8 + il) * (TNSTR*4) + ecol * 2);
                asm volatile(
                    "ldmatrix.sync.aligned.m8n8.x4.trans.shared.b16 "
                    "{%0,%1,%2,%3},[%4];"
                    : "=r"(af[mt][0]), "=r"(af[mt][1]),
                      "=r"(af[mt][2]), "=r"(af[mt][3]) : "r"(ad));
            }
#pragma unroll
            for (int nt = 0; nt < 4; nt++) {
                const int ncol = wn + nt * 8;
                unsigned ad = bbase
                    + (unsigned)((kc0 + q2 * 8 + il) * (TNSTR*4) + ncol * 2);
                asm volatile(
                    "ldmatrix.sync.aligned.m8n8.x2.trans.shared.b16 "
                    "{%0,%1},[%2];"
                    : "=r"(bf[nt][0]), "=r"(bf[nt][1]) : "r"(ad));
            }
#pragma unroll
            for (int mt = 0; mt < 4; mt++)
#pragma unroll
                for (int nt = 0; nt < 4; nt++)
                    mma16(acc[mt][nt], af[mt], bf[nt]);
        }
        __syncthreads();
    }

    float* Cp = g_Spart + (size_t)(sk * B_ + b) * E_ * D_;
#pragma unroll
    for (int mt = 0; mt < 4; mt++)
#pragma unroll
        for (int nt = 0; nt < 4; nt++) {
            const int d = d0 + wn + nt * 8 + 2 * qt;
#pragma unroll
            for (int rh = 0; rh < 2; rh++) {
                const int e = e0 + wm + mt * 16 + g + rh * 8;
                *(float2*)(Cp + (size_t)e * D_ + d) =
                    make_float2(acc[mt][nt][rh*2], acc[mt][nt][rh*2+1]);
            }
        }
}

// deterministic split-K reduction
__global__ void reduce_S()
{
    const int i = blockIdx.x * 256 + threadIdx.x;
    const int N4 = B_*E_*D_/4;
    const float4* p = (const float4*)g_Spart;
    float4 a = p[i], b = p[i + N4], c = p[i + 2*N4], d = p[i + 3*N4];
    ((float4*)g_S)[i] = make_float4(a.x+b.x+c.x+d.x, a.y+b.y+c.y+d.y,
                                    a.z+b.z+c.z+d.z, a.w+b.w+c.w+d.w);
}

// ---------------- flash attention: full fp16 (QK + PV), fp32 softmax -------
// grid (16 q-tiles, 32 bh), block 128 (4 warps). Warp owns 32 q rows.
// K,V fp16 in smem [row][40 halves] (20-word stride, conflict-free).
// QK: mma16, B-frags = plain LDS.32 of packed k-pairs. PV: acc->A pack + ldmatrix.
#define FTK 64
#define KVW 20      // words per K/V row (40 halves; rows 80B, 16B-aligned)

__global__ __launch_bounds__(128, 3)
void flash_attn_f16()
{
    __shared__ __align__(16) unsigned Ks16[FTK*KVW];
    __shared__ __align__(16) unsigned Vs16[FTK*KVW];

    const int t = threadIdx.x, lane = t & 31, w = t >> 5;
    const int g = lane >> 2, qt = lane & 3;
    const int bh = blockIdx.y;
    const int qbase = blockIdx.x * 128 + w * 32;

    const float scale = 0.17677669529663687f;   // 1/sqrt(32)
    const float* qp = g_q + ((size_t)bh * M_ + qbase) * DH_;

    // Q A-fragments, fp16, scale folded in. qf[mt][ks] covers k16 chunk ks.
    unsigned qf[2][2][4];
#pragma unroll
    for (int mt = 0; mt < 2; mt++)
#pragma unroll
        for (int ks = 0; ks < 2; ks++) {
            int r0 = mt * 16 + g, c0 = ks * 16 + 2 * qt;
            qf[mt][ks][0] = pk16(scale*qp[r0*32 + c0],       scale*qp[r0*32 + c0 + 1]);
            qf[mt][ks][1] = pk16(scale*qp[(r0+8)*32 + c0],   scale*qp[(r0+8)*32 + c0 + 1]);
            qf[mt][ks][2] = pk16(scale*qp[r0*32 + c0 + 8],   scale*qp[r0*32 + c0 + 9]);
            qf[mt][ks][3] = pk16(scale*qp[(r0+8)*32 + c0+8], scale*qp[(r0+8)*32 + c0+9]);
        }

    float of[2][4][4];
#pragma unroll
    for (int i = 0; i < 2; i++)
#pragma unroll
        for (int j = 0; j < 4; j++)
#pragma unroll
            for (int r = 0; r < 4; r++) of[i][j][r] = 0.f;
    float mr[2][2] = {{-1e30f,-1e30f},{-1e30f,-1e30f}};
    float lr[2][2] = {{0.f,0.f},{0.f,0.f}};

    const float* kb = g_k + (size_t)bh * M_ * DH_;
    const float* vb = g_v + (size_t)bh * M_ * DH_;

    const unsigned vsbase = (unsigned)__cvta_generic_to_shared(Vs16);
    const int ldkr = (lane & 7) + 8 * ((lane >> 3) & 1);

    for (int kt = 0; kt < M_; kt += FTK) {
        __syncthreads();
#pragma unroll
        for (int p = 0; p < 4; p++) {
            int linear = p * 512 + t * 4;
            int r = linear >> 5, c = linear & 31;
            float4 kv = *(const float4*)(kb + (size_t)(kt + r) * DH_ + c);
            Ks16[r*KVW + c/2]     = pk16(kv.x, kv.y);
            Ks16[r*KVW + c/2 + 1] = pk16(kv.z, kv.w);
            float4 vv = *(const float4*)(vb + (size_t)(kt + r) * DH_ + c);
            Vs16[r*KVW + c/2]     = pk16(vv.x, vv.y);
            Vs16[r*KVW + c/2 + 1] = pk16(vv.z, vv.w);
        }
        __syncthreads();

        // S = Q @ K^T  (32q x 64keys, fp16 mma16)
        float sf[2][8][4];
#pragma unroll
        for (int i = 0; i < 2; i++)
#pragma unroll
            for (int j = 0; j < 8; j++)
#pragma unroll
                for (int r = 0; r < 4; r++) sf[i][j][r] = 0.f;
#pragma unroll
        for (int ks = 0; ks < 2; ks++) {
            unsigned bfk[8][2];
            const int kw = ks * 8 + qt;
#pragma unroll
            for (int n = 0; n < 8; n++) {
                bfk[n][0] = Ks16[(n*8 + g)*KVW + kw];
                bfk[n][1] = Ks16[(n*8 + g)*KVW + kw + 4];
            }
#pragma unroll
            for (int mt = 0; mt < 2; mt++)
#pragma unroll
                for (int n = 0; n < 8; n++)
                    mma16(sf[mt][n], qf[mt][ks], bfk[n]);
        }

        // online softmax on fragments (fp32); overwrite sf with exp values
#pragma unroll
        for (int mt = 0; mt < 2; mt++) {
#pragma unroll
            for (int rh = 0; rh < 2; rh++) {
                float mx = -1e30f;
#pragma unroll
                for (int n = 0; n < 8; n++) {
                    mx = fmaxf(mx, sf[mt][n][rh*2]);
                    mx = fmaxf(mx, sf[mt][n][rh*2+1]);
                }
                mx = fmaxf(mx, __shfl_xor_sync(~0u, mx, 1));
                mx = fmaxf(mx, __shfl_xor_sync(~0u, mx, 2));
                float mn = fmaxf(mr[mt][rh], mx);
                float corr = __expf(mr[mt][rh] - mn);
                mr[mt][rh] = mn;
                lr[mt][rh] *= corr;
#pragma unroll
                for (int nd = 0; nd < 4; nd++) {
                    of[mt][nd][rh*2]   *= corr;
                    of[mt][nd][rh*2+1] *= corr;
                }
                float ls = 0.f;
#pragma unroll
                for (int n = 0; n < 8; n++) {
                    float e0 = __expf(sf[mt][n][rh*2]   - mn);
                    float e1 = __expf(sf[mt][n][rh*2+1] - mn);
                    ls += e0 + e1;
                    sf[mt][n][rh*2] = e0; sf[mt][n][rh*2+1] = e1;
                }
                lr[mt][rh] += ls;
            }
        }

        // O += P @ V : fp16 m16n8k16; A-frags pack straight from S-acc
#pragma unroll
        for (int j = 0; j < 4; j++) {
            unsigned bfv[4][2];
            const int kr = 16*j + ldkr;
#pragma unroll
            for (int nd = 0; nd < 4; nd++) {
                unsigned ad = vsbase + (unsigned)(kr * (KVW*4) + nd * 16);
                asm volatile(
                    "ldmatrix.sync.aligned.m8n8.x2.trans.shared.b16 {%0,%1},[%2];"
                    : "=r"(bfv[nd][0]), "=r"(bfv[nd][1]) : "r"(ad));
            }
#pragma unroll
            for (int mt = 0; mt < 2; mt++) {
                unsigned af[4];
                af[0] = pk16(sf[mt][2*j][0],   sf[mt][2*j][1]);
                af[1] = pk16(sf[mt][2*j][2],   sf[mt][2*j][3]);
                af[2] = pk16(sf[mt][2*j+1][0], sf[mt][2*j+1][1]);
                af[3] = pk16(sf[mt][2*j+1][2], sf[mt][2*j+1][3]);
#pragma unroll
                for (int nd = 0; nd < 4; nd++)
                    mma16(of[mt][nd], af, bfv[nd]);
            }
        }
    }

    // finalize + store into g_attn [b][m][h*32 + d]
    const int b = bh >> 3, h = bh & 7;
#pragma unroll
    for (int mt = 0; mt < 2; mt++)
#pragma unroll
        for (int rh = 0; rh < 2; rh++) {
            float l = lr[mt][rh];
            l += __shfl_xor_sync(~0u, l, 1);
            l += __shfl_xor_sync(~0u, l, 2);
            float inv = 1.f / l;
            const int q = qbase + mt*16 + g + rh*8;
            float* op = g_attn + ((size_t)b * M_ + q) * D_ + h * DH_;
#pragma unroll
            for (int nd = 0; nd < 4; nd++)
                *(float2*)(op + nd*8 + 2*qt) =
                    make_float2(of[mt][nd][rh*2]*inv, of[mt][nd][rh*2+1]*inv);
        }
}

// ---------------- softmax over hyperedge dim + ef = S*W --------------------
__global__ void softmax_e()
{
    const int t = threadIdx.x, lane = t & 31, wid = t >> 5;
    const int col = blockIdx.x * 8 + wid;
    const int b = col >> 8, d = col & 255;
    const float* base = g_S + (size_t)b * E_ * D_ + d;
    float v[32];
    float mx = -1e30f;
#pragma unroll
    for (int r = 0; r < 32; r++) {
        float x = base[(size_t)(lane + r*32) * D_];
        v[r] = x; mx = fmaxf(mx, x);
    }
#pragma unroll
    for (int off = 16; off; off >>= 1) mx = fmaxf(mx, __shfl_xor_sync(~0u, mx, off));
    float se = 0.f;
#pragma unroll
    for (int r = 0; r < 32; r++) se += __expf(v[r] - mx);
#pragma unroll
    for (int off = 16; off; off >>= 1) se += __shfl_xor_sync(~0u, se, off);
    float inv = 1.f / se;
    float* ob = g_ef + (size_t)b * E_ * D_ + d;
#pragma unroll
    for (int r = 0; r < 32; r++)
        ob[(size_t)(lane + r*32) * D_] = v[r] * __expf(v[r] - mx) * inv;
}

// ---------------- LayerNorm + residual -------------------------------------
__global__ void ln_residual(const float* __restrict__ prev,
                            const float* __restrict__ gamma,
                            const float* __restrict__ beta,
                            const float* __restrict__ alphap,
                            float* __restrict__ out)
{
    const int t = threadIdx.x, lane = t & 31, wid = t >> 5;
    const int row = blockIdx.x * 8 + wid;
    const float* x = g_ef2 + (size_t)row * D_;
    float xs[8], sum = 0.f, sq = 0.f;
#pragma unroll
    for (int c = 0; c < 8; c++) {
        float v = x[lane + c*32];
        xs[c] = v; sum += v; sq += v*v;
    }
#pragma unroll
    for (int off = 16; off; off >>= 1) {
        sum += __shfl_xor_sync(~0u, sum, off);
        sq  += __shfl_xor_sync(~0u, sq,  off);
    }
    const float mu   = sum * (1.f / D_);
    const float var  = sq * (1.f / D_) - mu * mu;
    const float rstd = rsqrtf(var + 1e-5f);
    const float alpha = *alphap;
#pragma unroll
    for (int c = 0; c < 8; c++) {
        int d = lane + c*32;
        float y = (xs[c] - mu) * rstd * gamma[d] + beta[d];
        size_t idx = (size_t)row * D_ + d;
        out[idx] = (1.f + alpha) * prev[idx] + (1.f - alpha) * y;
    }
}

// ---------------- launch ----------------------------------------------------
extern "C" void kernel_launch(void* const* d_in, const int* in_sizes, int n_in,
                              void* d_out, int out_size)
{
    const float* feature = (const float*)d_in[0];
    const float* inc     = (const float*)d_in[1];
    const float* prev    = (const float*)d_in[2];
    const float* inw     = (const float*)d_in[3];
    const float* inb     = (const float*)d_in[4];
    const float* outw    = (const float*)d_in[5];
    const float* outb    = (const float*)d_in[6];
    const float* projw   = (const float*)d_in[7];
    const float* gamma   = (const float*)d_in[8];
    const float* beta    = (const float*)d_in[9];
    const float* alphap  = (const float*)d_in[10];
    float* out = (float*)d_out;

    float *p_attn = 0, *p_attnout = 0, *p_ef = 0, *p_ef2 = 0;
    cudaGetSymbolAddress((void**)&p_attn,    g_attn);
    cudaGetSymbolAddress((void**)&p_attnout, g_attnout);
    cudaGetSymbolAddress((void**)&p_ef,      g_ef);
    cudaGetSymbolAddress((void**)&p_ef2,     g_ef2);

    // 1. QKV projection -> scatter to q/k/v
    gemm_nt_f16<1><<<dim3(6, 64), 256>>>(feature, inw, inb, (float*)0, B_*M_, 3*D_, D_);
    // 2. attention (full fp16 tensor path)
    flash_attn_f16<<<dim3(16, 32), 128>>>();
    // 3. out_proj
    gemm_nt_f16<0><<<dim3(2, 64), 256>>>(p_attn, outw, outb, p_attnout, B_*M_, D_, D_);
    // 4. S = inc^T @ attnout (split-K partials) + reduce
    gemm_tn_S_f16<<<dim3(2, 8, B_*SPLITK), 256>>>(inc);
    reduce_S<<<B_*E_*D_/4/256, 256>>>();
    // 5. softmax over e + ef = S*W
    softmax_e<<<128, 256>>>();
    // 6. final projection
    gemm_nt_f16<0><<<dim3(2, 32), 256>>>(p_ef, projw, (float*)0, p_ef2, B_*E_, D_, D_);
    // 7. LN + residual mix
    ln_residual<<<512, 256>>>(prev, gamma, beta, alphap, out);
}

// round 16
// speedup vs baseline: 2.1866x; 1.0576x over previous
#include <cuda_runtime.h>
#include <math.h>

#define B_ 4
#define M_ 2048
#define E_ 1024
#define D_ 256
#define H_ 8
#define DH_ 32
#define SPLITK 4
#define KCH (M_ / SPLITK)   // 512

// ---------------- scratch (device globals: allocation-free) ----------------
__device__ float g_q[B_*H_*M_*DH_];
__device__ float g_k[B_*H_*M_*DH_];
__device__ float g_v[B_*H_*M_*DH_];
__device__ float g_attn[B_*M_*D_];
__device__ float g_attnout[B_*M_*D_];
__device__ float g_Spart[SPLITK*B_*E_*D_];   // TRANSPOSED: [sk][b][d][e]
__device__ float g_ef[B_*E_*D_];             // TRANSPOSED: [b][d][e]
__device__ float g_ef2[B_*E_*D_];            // normal [b][e][dout]

// ---------------- helpers ---------------------------------------------------
__device__ __forceinline__ void mma16(float* d, const unsigned* a, const unsigned* b) {
    asm volatile(
        "mma.sync.aligned.m16n8k16.row.col.f32.f16.f16.f32 "
        "{%0,%1,%2,%3},{%4,%5,%6,%7},{%8,%9},{%0,%1,%2,%3};"
        : "+f"(d[0]), "+f"(d[1]), "+f"(d[2]), "+f"(d[3])
        : "r"(a[0]), "r"(a[1]), "r"(a[2]), "r"(a[3]), "r"(b[0]), "r"(b[1]));
}
__device__ __forceinline__ unsigned pk16(float lo, float hi) {
    unsigned r;
    asm("cvt.rn.f16x2.f32 %0, %1, %2;" : "=r"(r) : "f"(hi), "f"(lo));
    return r;
}

// ---------------- NT fp16 GEMM: C[M,N] = A[M,K] @ Bw[N,K]^T (+bias) --------
#define NTSTR 20
template<int EPI>
__global__ __launch_bounds__(256, 2)
void gemm_nt_f16(const float* __restrict__ A, const float* __restrict__ Bw,
                 const float* __restrict__ bias, float* __restrict__ C,
                 int M, int N, int K)
{
    __shared__ unsigned As[128*NTSTR];
    __shared__ unsigned Bs[128*NTSTR];
    const int t = threadIdx.x, lane = t & 31, w = t >> 5;
    const int m0 = blockIdx.y * 128, n0 = blockIdx.x * 128;
    const int wm = (w & 1) * 64, wn = (w >> 1) * 32;
    const int g = lane >> 2, qt = lane & 3;

    float acc[4][4][4];
#pragma unroll
    for (int i = 0; i < 4; i++)
#pragma unroll
        for (int j = 0; j < 4; j++)
#pragma unroll
            for (int r = 0; r < 4; r++) acc[i][j][r] = 0.f;

    for (int k0 = 0; k0 < K; k0 += 32) {
#pragma unroll
        for (int p = 0; p < 4; p++) {
            int lin = p * 1024 + t * 4;
            int r = lin >> 5, c = lin & 31;
            float4 av = *(const float4*)(A + (size_t)(m0 + r) * K + k0 + c);
            As[r*NTSTR + c/2]     = pk16(av.x, av.y);
            As[r*NTSTR + c/2 + 1] = pk16(av.z, av.w);
            float4 bv = *(const float4*)(Bw + (size_t)(n0 + r) * K + k0 + c);
            Bs[r*NTSTR + c/2]     = pk16(bv.x, bv.y);
            Bs[r*NTSTR + c/2 + 1] = pk16(bv.z, bv.w);
        }
        __syncthreads();
#pragma unroll
        for (int ks = 0; ks < 2; ks++) {
            const int kw = ks * 8 + qt;
            unsigned af[4][4], bf[4][2];
#pragma unroll
            for (int mt = 0; mt < 4; mt++) {
                const int mr = wm + mt * 16 + g;
                af[mt][0] = As[mr*NTSTR + kw];
                af[mt][1] = As[(mr+8)*NTSTR + kw];
                af[mt][2] = As[mr*NTSTR + kw + 4];
                af[mt][3] = As[(mr+8)*NTSTR + kw + 4];
            }
#pragma unroll
            for (int nt = 0; nt < 4; nt++) {
                const int nr = wn + nt * 8 + g;
                bf[nt][0] = Bs[nr*NTSTR + kw];
                bf[nt][1] = Bs[nr*NTSTR + kw + 4];
            }
#pragma unroll
            for (int mt = 0; mt < 4; mt++)
#pragma unroll
                for (int nt = 0; nt < 4; nt++)
                    mma16(acc[mt][nt], af[mt], bf[nt]);
        }
        __syncthreads();
    }

#pragma unroll
    for (int mt = 0; mt < 4; mt++) {
#pragma unroll
        for (int nt = 0; nt < 4; nt++) {
            const int n = n0 + wn + nt * 8 + 2 * qt;
            float b0 = bias ? bias[n] : 0.f;
            float b1 = bias ? bias[n+1] : 0.f;
#pragma unroll
            for (int rh = 0; rh < 2; rh++) {
                const int m = m0 + wm + mt * 16 + g + rh * 8;
                float v0 = acc[mt][nt][rh*2] + b0;
                float v1 = acc[mt][nt][rh*2+1] + b1;
                if (EPI == 0) {
                    *(float2*)(C + (size_t)m * N + n) = make_float2(v0, v1);
                } else {
                    int bi = m >> 11, mm = m & (M_ - 1);
                    int which = n >> 8, dd = n & 255;
                    int h = dd >> 5, c = dd & 31;
                    float* dst = (which == 0 ? g_q : which == 1 ? g_k : g_v)
                               + (size_t)(((bi << 3) + h) * M_ + mm) * DH_ + c;
                    *(float2*)dst = make_float2(v0, v1);
                }
            }
        }
    }
}

// ---------------- TN fp16 GEMM (split-K): S_partial^T = (inc^T@attnout)^T --
// epilogue stores TRANSPOSED [d][e]: warp writes 8 consecutive-e lanes per
// d-group -> exact 32B sectors.
#define TNSTR 68
__global__ __launch_bounds__(256, 2)
void gemm_tn_S_f16(const float* __restrict__ inc)
{
    __shared__ unsigned As[32*TNSTR];
    __shared__ unsigned Bs[32*TNSTR];
    const int t = threadIdx.x, lane = t & 31, w = t >> 5;
    const int z = blockIdx.z;
    const int b = z >> 2, sk = z & 3;
    const int e0 = blockIdx.y * 128, d0 = blockIdx.x * 128;
    const int kbase = sk * KCH;
    const int wm = (w & 1) * 64, wn = (w >> 1) * 32;
    const int g = lane >> 2, qt = lane & 3;
    const float* Ag = inc       + (size_t)b * M_ * E_;
    const float* Bg = g_attnout + (size_t)b * M_ * D_;

    const unsigned abase = (unsigned)__cvta_generic_to_shared(As);
    const unsigned bbase = (unsigned)__cvta_generic_to_shared(Bs);
    const int il = lane & 7, qq = lane >> 3;
    const int q2 = (lane >> 3) & 1;

    float acc[4][4][4];
#pragma unroll
    for (int i = 0; i < 4; i++)
#pragma unroll
        for (int j = 0; j < 4; j++)
#pragma unroll
            for (int r = 0; r < 4; r++) acc[i][j][r] = 0.f;

    for (int k0 = 0; k0 < KCH; k0 += 32) {
#pragma unroll
        for (int p = 0; p < 4; p++) {
            int lin = p * 1024 + t * 4;
            int r = lin >> 7, c = lin & 127;
            int krow = kbase + k0 + r;
            float4 av = *(const float4*)(Ag + (size_t)krow * E_ + e0 + c);
            As[r*TNSTR + c/2]     = pk16(av.x, av.y);
            As[r*TNSTR + c/2 + 1] = pk16(av.z, av.w);
            float4 bv = *(const float4*)(Bg + (size_t)krow * D_ + d0 + c);
            Bs[r*TNSTR + c/2]     = pk16(bv.x, bv.y);
            Bs[r*TNSTR + c/2 + 1] = pk16(bv.z, bv.w);
        }
        __syncthreads();
#pragma unroll
        for (int ks = 0; ks < 2; ks++) {
            const int kc0 = ks * 16;
            unsigned af[4][4], bf[4][2];
#pragma unroll
            for (int mt = 0; mt < 4; mt++) {
                const int ecol = wm + mt * 16 + (qq & 1) * 8;
                unsigned ad = abase
                    + (unsigned)((kc0 + (qq >> 1) * 8 + il) * (TNSTR*4) + ecol * 2);
                asm volatile(
                    "ldmatrix.sync.aligned.m8n8.x4.trans.shared.b16 "
                    "{%0,%1,%2,%3},[%4];"
                    : "=r"(af[mt][0]), "=r"(af[mt][1]),
                      "=r"(af[mt][2]), "=r"(af[mt][3]) : "r"(ad));
            }
#pragma unroll
            for (int nt = 0; nt < 4; nt++) {
                const int ncol = wn + nt * 8;
                unsigned ad = bbase
                    + (unsigned)((kc0 + q2 * 8 + il) * (TNSTR*4) + ncol * 2);
                asm volatile(
                    "ldmatrix.sync.aligned.m8n8.x2.trans.shared.b16 "
                    "{%0,%1},[%2];"
                    : "=r"(bf[nt][0]), "=r"(bf[nt][1]) : "r"(ad));
            }
#pragma unroll
            for (int mt = 0; mt < 4; mt++)
#pragma unroll
                for (int nt = 0; nt < 4; nt++)
                    mma16(acc[mt][nt], af[mt], bf[nt]);
        }
        __syncthreads();
    }

    // transposed store: Cp[d][e]
    float* Cp = g_Spart + (size_t)(sk * B_ + b) * E_ * D_;
#pragma unroll
    for (int mt = 0; mt < 4; mt++)
#pragma unroll
        for (int nt = 0; nt < 4; nt++) {
            const int d = d0 + wn + nt * 8 + 2 * qt;
#pragma unroll
            for (int rh = 0; rh < 2; rh++) {
                const int e = e0 + wm + mt * 16 + g + rh * 8;
                Cp[(size_t)d * E_ + e]       = acc[mt][nt][rh*2];
                Cp[(size_t)(d+1) * E_ + e]   = acc[mt][nt][rh*2+1];
            }
        }
}

// ---------------- fused split-K reduce + softmax over e + ef = S*W ---------
// warp per (b,d) row; partials and output are [d][e] (contiguous rows).
// g_S never materializes.
__global__ void softmax_fused()
{
    const int t = threadIdx.x, lane = t & 31, wid = t >> 5;
    const int col = blockIdx.x * 8 + wid;           // 0..1023
    const int b = col >> 8, d = col & 255;
    const size_t NB = (size_t)B_ * E_ * D_;
    const float* p0 = g_Spart + (size_t)b * E_ * D_ + (size_t)d * E_;

    float4 v[8];
    float mx = -1e30f;
#pragma unroll
    for (int r = 0; r < 8; r++) {
        const int e4 = lane + r * 32;               // float4 index in row
        float4 a = *(const float4*)(p0 + e4*4);
        float4 b1 = *(const float4*)(p0 + NB + e4*4);
        float4 c = *(const float4*)(p0 + 2*NB + e4*4);
        float4 dd = *(const float4*)(p0 + 3*NB + e4*4);
        float4 s = make_float4(a.x+b1.x+c.x+dd.x, a.y+b1.y+c.y+dd.y,
                               a.z+b1.z+c.z+dd.z, a.w+b1.w+c.w+dd.w);
        v[r] = s;
        mx = fmaxf(mx, fmaxf(fmaxf(s.x, s.y), fmaxf(s.z, s.w)));
    }
#pragma unroll
    for (int off = 16; off; off >>= 1) mx = fmaxf(mx, __shfl_xor_sync(~0u, mx, off));

    float4 ev[8];
    float se = 0.f;
#pragma unroll
    for (int r = 0; r < 8; r++) {
        ev[r].x = __expf(v[r].x - mx); ev[r].y = __expf(v[r].y - mx);
        ev[r].z = __expf(v[r].z - mx); ev[r].w = __expf(v[r].w - mx);
        se += ev[r].x + ev[r].y + ev[r].z + ev[r].w;
    }
#pragma unroll
    for (int off = 16; off; off >>= 1) se += __shfl_xor_sync(~0u, se, off);
    const float inv = 1.f / se;

    float* ob = g_ef + (size_t)b * E_ * D_ + (size_t)d * E_;
#pragma unroll
    for (int r = 0; r < 8; r++) {
        const int e4 = lane + r * 32;
        *(float4*)(ob + e4*4) = make_float4(v[r].x*ev[r].x*inv, v[r].y*ev[r].y*inv,
                                            v[r].z*ev[r].z*inv, v[r].w*ev[r].w*inv);
    }
}

// ---------------- hybrid TN proj: C[e][n] = efT[k=d][e] ^T @ projw[n][k]^T --
// A-frags: ldmatrix x4 trans on [k][m] smem (gemm_tn_S path).
// B-frags: direct LDS on [n][k] smem (gemm_nt path).
__global__ __launch_bounds__(256, 2)
void gemm_proj_f16(const float* __restrict__ Bw, float* __restrict__ C)
{
    __shared__ unsigned As[32*TNSTR];   // [k][e] fp16 pairs
    __shared__ unsigned Bs[128*NTSTR];  // [n][k] fp16 pairs
    const int t = threadIdx.x, lane = t & 31, w = t >> 5;
    const int b = blockIdx.z;
    const int m0 = blockIdx.y * 128, n0 = blockIdx.x * 128;  // m = e
    const int wm = (w & 1) * 64, wn = (w >> 1) * 32;
    const int g = lane >> 2, qt = lane & 3;
    const float* Ag = g_ef + (size_t)b * E_ * D_;   // [d][e]

    const unsigned abase = (unsigned)__cvta_generic_to_shared(As);
    const int il = lane & 7, qq = lane >> 3;

    float acc[4][4][4];
#pragma unroll
    for (int i = 0; i < 4; i++)
#pragma unroll
        for (int j = 0; j < 4; j++)
#pragma unroll
            for (int r = 0; r < 4; r++) acc[i][j][r] = 0.f;

    for (int k0 = 0; k0 < D_; k0 += 32) {
        // A: [32 k][128 e]
#pragma unroll
        for (int p = 0; p < 4; p++) {
            int lin = p * 1024 + t * 4;
            int r = lin >> 7, c = lin & 127;
            float4 av = *(const float4*)(Ag + (size_t)(k0 + r) * E_ + m0 + c);
            As[r*TNSTR + c/2]     = pk16(av.x, av.y);
            As[r*TNSTR + c/2 + 1] = pk16(av.z, av.w);
        }
        // B: [128 n][32 k]
#pragma unroll
        for (int p = 0; p < 4; p++) {
            int lin = p * 1024 + t * 4;
            int r = lin >> 5, c = lin & 31;
            float4 bv = *(const float4*)(Bw + (size_t)(n0 + r) * D_ + k0 + c);
            Bs[r*NTSTR + c/2]     = pk16(bv.x, bv.y);
            Bs[r*NTSTR + c/2 + 1] = pk16(bv.z, bv.w);
        }
        __syncthreads();
#pragma unroll
        for (int ks = 0; ks < 2; ks++) {
            const int kc0 = ks * 16;
            const int kw = ks * 8 + qt;
            unsigned af[4][4], bf[4][2];
#pragma unroll
            for (int mt = 0; mt < 4; mt++) {
                const int ecol = wm + mt * 16 + (qq & 1) * 8;
                unsigned ad = abase
                    + (unsigned)((kc0 + (qq >> 1) * 8 + il) * (TNSTR*4) + ecol * 2);
                asm volatile(
                    "ldmatrix.sync.aligned.m8n8.x4.trans.shared.b16 "
                    "{%0,%1,%2,%3},[%4];"
                    : "=r"(af[mt][0]), "=r"(af[mt][1]),
                      "=r"(af[mt][2]), "=r"(af[mt][3]) : "r"(ad));
            }
#pragma unroll
            for (int nt = 0; nt < 4; nt++) {
                const int nr = wn + nt * 8 + g;
                bf[nt][0] = Bs[nr*NTSTR + kw];
                bf[nt][1] = Bs[nr*NTSTR + kw + 4];
            }
#pragma unroll
            for (int mt = 0; mt < 4; mt++)
#pragma unroll
                for (int nt = 0; nt < 4; nt++)
                    mma16(acc[mt][nt], af[mt], bf[nt]);
        }
        __syncthreads();
    }

    float* Cb = C + (size_t)b * E_ * D_;
#pragma unroll
    for (int mt = 0; mt < 4; mt++)
#pragma unroll
        for (int nt = 0; nt < 4; nt++) {
            const int n = n0 + wn + nt * 8 + 2 * qt;
#pragma unroll
            for (int rh = 0; rh < 2; rh++) {
                const int m = m0 + wm + mt * 16 + g + rh * 8;
                *(float2*)(Cb + (size_t)m * D_ + n) =
                    make_float2(acc[mt][nt][rh*2], acc[mt][nt][rh*2+1]);
            }
        }
}

// ---------------- flash attention: full fp16 (unchanged from R15) ----------
#define FTK 64
#define KVW 20

__global__ __launch_bounds__(128, 3)
void flash_attn_f16()
{
    __shared__ __align__(16) unsigned Ks16[FTK*KVW];
    __shared__ __align__(16) unsigned Vs16[FTK*KVW];

    const int t = threadIdx.x, lane = t & 31, w = t >> 5;
    const int g = lane >> 2, qt = lane & 3;
    const int bh = blockIdx.y;
    const int qbase = blockIdx.x * 128 + w * 32;

    const float scale = 0.17677669529663687f;
    const float* qp = g_q + ((size_t)bh * M_ + qbase) * DH_;

    unsigned qf[2][2][4];
#pragma unroll
    for (int mt = 0; mt < 2; mt++)
#pragma unroll
        for (int ks = 0; ks < 2; ks++) {
            int r0 = mt * 16 + g, c0 = ks * 16 + 2 * qt;
            qf[mt][ks][0] = pk16(scale*qp[r0*32 + c0],       scale*qp[r0*32 + c0 + 1]);
            qf[mt][ks][1] = pk16(scale*qp[(r0+8)*32 + c0],   scale*qp[(r0+8)*32 + c0 + 1]);
            qf[mt][ks][2] = pk16(scale*qp[r0*32 + c0 + 8],   scale*qp[r0*32 + c0 + 9]);
            qf[mt][ks][3] = pk16(scale*qp[(r0+8)*32 + c0+8], scale*qp[(r0+8)*32 + c0+9]);
        }

    float of[2][4][4];
#pragma unroll
    for (int i = 0; i < 2; i++)
#pragma unroll
        for (int j = 0; j < 4; j++)
#pragma unroll
            for (int r = 0; r < 4; r++) of[i][j][r] = 0.f;
    float mr[2][2] = {{-1e30f,-1e30f},{-1e30f,-1e30f}};
    float lr[2][2] = {{0.f,0.f},{0.f,0.f}};

    const float* kb = g_k + (size_t)bh * M_ * DH_;
    const float* vb = g_v + (size_t)bh * M_ * DH_;

    const unsigned vsbase = (unsigned)__cvta_generic_to_shared(Vs16);
    const int ldkr = (lane & 7) + 8 * ((lane >> 3) & 1);

    for (int kt = 0; kt < M_; kt += FTK) {
        __syncthreads();
#pragma unroll
        for (int p = 0; p < 4; p++) {
            int linear = p * 512 + t * 4;
            int r = linear >> 5, c = linear & 31;
            float4 kv = *(const float4*)(kb + (size_t)(kt + r) * DH_ + c);
            Ks16[r*KVW + c/2]     = pk16(kv.x, kv.y);
            Ks16[r*KVW + c/2 + 1] = pk16(kv.z, kv.w);
            float4 vv = *(const float4*)(vb + (size_t)(kt + r) * DH_ + c);
            Vs16[r*KVW + c/2]     = pk16(vv.x, vv.y);
            Vs16[r*KVW + c/2 + 1] = pk16(vv.z, vv.w);
        }
        __syncthreads();

        float sf[2][8][4];
#pragma unroll
        for (int i = 0; i < 2; i++)
#pragma unroll
            for (int j = 0; j < 8; j++)
#pragma unroll
                for (int r = 0; r < 4; r++) sf[i][j][r] = 0.f;
#pragma unroll
        for (int ks = 0; ks < 2; ks++) {
            unsigned bfk[8][2];
            const int kw = ks * 8 + qt;
#pragma unroll
            for (int n = 0; n < 8; n++) {
                bfk[n][0] = Ks16[(n*8 + g)*KVW + kw];
                bfk[n][1] = Ks16[(n*8 + g)*KVW + kw + 4];
            }
#pragma unroll
            for (int mt = 0; mt < 2; mt++)
#pragma unroll
                for (int n = 0; n < 8; n++)
                    mma16(sf[mt][n], qf[mt][ks], bfk[n]);
        }

#pragma unroll
        for (int mt = 0; mt < 2; mt++) {
#pragma unroll
            for (int rh = 0; rh < 2; rh++) {
                float mx = -1e30f;
#pragma unroll
                for (int n = 0; n < 8; n++) {
                    mx = fmaxf(mx, sf[mt][n][rh*2]);
                    mx = fmaxf(mx, sf[mt][n][rh*2+1]);
                }
                mx = fmaxf(mx, __shfl_xor_sync(~0u, mx, 1));
                mx = fmaxf(mx, __shfl_xor_sync(~0u, mx, 2));
                float mn = fmaxf(mr[mt][rh], mx);
                float corr = __expf(mr[mt][rh] - mn);
                mr[mt][rh] = mn;
                lr[mt][rh] *= corr;
#pragma unroll
                for (int nd = 0; nd < 4; nd++) {
                    of[mt][nd][rh*2]   *= corr;
                    of[mt][nd][rh*2+1] *= corr;
                }
                float ls = 0.f;
#pragma unroll
                for (int n = 0; n < 8; n++) {
                    float e0 = __expf(sf[mt][n][rh*2]   - mn);
                    float e1 = __expf(sf[mt][n][rh*2+1] - mn);
                    ls += e0 + e1;
                    sf[mt][n][rh*2] = e0; sf[mt][n][rh*2+1] = e1;
                }
                lr[mt][rh] += ls;
            }
        }

#pragma unroll
        for (int j = 0; j < 4; j++) {
            unsigned bfv[4][2];
            const int kr = 16*j + ldkr;
#pragma unroll
            for (int nd = 0; nd < 4; nd++) {
                unsigned ad = vsbase + (unsigned)(kr * (KVW*4) + nd * 16);
                asm volatile(
                    "ldmatrix.sync.aligned.m8n8.x2.trans.shared.b16 {%0,%1},[%2];"
                    : "=r"(bfv[nd][0]), "=r"(bfv[nd][1]) : "r"(ad));
            }
#pragma unroll
            for (int mt = 0; mt < 2; mt++) {
                unsigned af[4];
                af[0] = pk16(sf[mt][2*j][0],   sf[mt][2*j][1]);
                af[1] = pk16(sf[mt][2*j][2],   sf[mt][2*j][3]);
                af[2] = pk16(sf[mt][2*j+1][0], sf[mt][2*j+1][1]);
                af[3] = pk16(sf[mt][2*j+1][2], sf[mt][2*j+1][3]);
#pragma unroll
                for (int nd = 0; nd < 4; nd++)
                    mma16(of[mt][nd], af, bfv[nd]);
            }
        }
    }

    const int b = bh >> 3, h = bh & 7;
#pragma unroll
    for (int mt = 0; mt < 2; mt++)
#pragma unroll
        for (int rh = 0; rh < 2; rh++) {
            float l = lr[mt][rh];
            l += __shfl_xor_sync(~0u, l, 1);
            l += __shfl_xor_sync(~0u, l, 2);
            float inv = 1.f / l;
            const int q = qbase + mt*16 + g + rh*8;
            float* op = g_attn + ((size_t)b * M_ + q) * D_ + h * DH_;
#pragma unroll
            for (int nd = 0; nd < 4; nd++)
                *(float2*)(op + nd*8 + 2*qt) =
                    make_float2(of[mt][nd][rh*2]*inv, of[mt][nd][rh*2+1]*inv);
        }
}

// ---------------- LayerNorm + residual -------------------------------------
__global__ void ln_residual(const float* __restrict__ prev,
                            const float* __restrict__ gamma,
                            const float* __restrict__ beta,
                            const float* __restrict__ alphap,
                            float* __restrict__ out)
{
    const int t = threadIdx.x, lane = t & 31, wid = t >> 5;
    const int row = blockIdx.x * 8 + wid;
    const float* x = g_ef2 + (size_t)row * D_;
    float xs[8], sum = 0.f, sq = 0.f;
#pragma unroll
    for (int c = 0; c < 8; c++) {
        float v = x[lane + c*32];
        xs[c] = v; sum += v; sq += v*v;
    }
#pragma unroll
    for (int off = 16; off; off >>= 1) {
        sum += __shfl_xor_sync(~0u, sum, off);
        sq  += __shfl_xor_sync(~0u, sq,  off);
    }
    const float mu   = sum * (1.f / D_);
    const float var  = sq * (1.f / D_) - mu * mu;
    const float rstd = rsqrtf(var + 1e-5f);
    const float alpha = *alphap;
#pragma unroll
    for (int c = 0; c < 8; c++) {
        int d = lane + c*32;
        float y = (xs[c] - mu) * rstd * gamma[d] + beta[d];
        size_t idx = (size_t)row * D_ + d;
        out[idx] = (1.f + alpha) * prev[idx] + (1.f - alpha) * y;
    }
}

// ---------------- launch ----------------------------------------------------
extern "C" void kernel_launch(void* const* d_in, const int* in_sizes, int n_in,
                              void* d_out, int out_size)
{
    const float* feature = (const float*)d_in[0];
    const float* inc     = (const float*)d_in[1];
    const float* prev    = (const float*)d_in[2];
    const float* inw     = (const float*)d_in[3];
    const float* inb     = (const float*)d_in[4];
    const float* outw    = (const float*)d_in[5];
    const float* outb    = (const float*)d_in[6];
    const float* projw   = (const float*)d_in[7];
    const float* gamma   = (const float*)d_in[8];
    const float* beta    = (const float*)d_in[9];
    const float* alphap  = (const float*)d_in[10];
    float* out = (float*)d_out;

    float *p_attn = 0, *p_attnout = 0, *p_ef2 = 0;
    cudaGetSymbolAddress((void**)&p_attn,    g_attn);
    cudaGetSymbolAddress((void**)&p_attnout, g_attnout);
    cudaGetSymbolAddress((void**)&p_ef2,     g_ef2);

    // 1. QKV projection -> scatter to q/k/v
    gemm_nt_f16<1><<<dim3(6, 64), 256>>>(feature, inw, inb, (float*)0, B_*M_, 3*D_, D_);
    // 2. attention (full fp16 tensor path)
    flash_attn_f16<<<dim3(16, 32), 128>>>();
    // 3. out_proj
    gemm_nt_f16<0><<<dim3(2, 64), 256>>>(p_attn, outw, outb, p_attnout, B_*M_, D_, D_);
    // 4. S^T = (inc^T @ attnout)^T  (split-K partials, transposed [d][e])
    gemm_tn_S_f16<<<dim3(2, 8, B_*SPLITK), 256>>>(inc);
    // 5. fused reduce + softmax over e + ef = S*W  (all contiguous rows)
    softmax_fused<<<128, 256>>>();
    // 6. final projection (hybrid TN: A = ef^T [d][e], B = projw [n][k])
    gemm_proj_f16<<<dim3(2, 8, B_), 256>>>(projw, p_ef2);
    // 7. LN + residual mix
    ln_residual<<<512, 256>>>(prev, gamma, beta, alphap, out);
}